// round 11
// baseline (speedup 1.0000x reference)
#include <cuda_runtime.h>
#include <cuda_bf16.h>
#include <math.h>
#include <stdint.h>

#define B_ 4
#define T_ 1024
#define C_ 1024
#define H_ 16
#define HD 64

// ---------------- scratch (static device globals; no allocation) -------------
__device__ __align__(16) float g_qkv[(size_t)4096 * 3072];
__device__ float g_q0[(size_t)B_ * H_ * T_];
__device__ float g_k0[(size_t)B_ * H_ * T_];
__device__ __align__(16) __nv_bfloat16 g_xh[(size_t)4096 * 1024];
__device__ __align__(16) __nv_bfloat16 g_xl[(size_t)4096 * 1024];
__device__ __align__(16) __nv_bfloat16 g_w1h[(size_t)3072 * 1024];
__device__ __align__(16) __nv_bfloat16 g_w1l[(size_t)3072 * 1024];
__device__ __align__(16) __nv_bfloat16 g_w2h[(size_t)1024 * 1024];
__device__ __align__(16) __nv_bfloat16 g_w2l[(size_t)1024 * 1024];
__device__ __align__(16) __nv_bfloat16 g_qh[(size_t)4096 * 1024];
__device__ __align__(16) __nv_bfloat16 g_ql[(size_t)4096 * 1024];
__device__ __align__(16) __nv_bfloat16 g_kh[(size_t)4096 * 1024];
__device__ __align__(16) __nv_bfloat16 g_kl[(size_t)4096 * 1024];
__device__ __align__(16) __nv_bfloat16 g_vh[(size_t)4096 * 1024];
__device__ __align__(16) __nv_bfloat16 g_vl[(size_t)4096 * 1024];
__device__ __align__(16) __nv_bfloat16 g_oh[(size_t)4096 * 1024];
__device__ __align__(16) __nv_bfloat16 g_ol[(size_t)4096 * 1024];

// ---------------- helpers ------------------------------------------------------
__device__ __forceinline__ uint32_t smem_u32(const void* p) {
    uint32_t a;
    asm("{ .reg .u64 t; cvta.to.shared.u64 t, %1; cvt.u32.u64 %0, t; }" : "=r"(a) : "l"(p));
    return a;
}
#define CP_ASYNC16(d, s)  asm volatile("cp.async.cg.shared.global [%0], [%1], 16;" :: "r"(d), "l"(s))
#define CP_COMMIT()       asm volatile("cp.async.commit_group;" ::: "memory")
#define CP_WAIT(n)        asm volatile("cp.async.wait_group %0;" :: "n"(n) : "memory")

__device__ __forceinline__ void ldm_x4(uint32_t& r0, uint32_t& r1, uint32_t& r2, uint32_t& r3,
                                       uint32_t addr) {
    asm volatile("ldmatrix.sync.aligned.m8n8.x4.shared.b16 {%0,%1,%2,%3}, [%4];"
                 : "=r"(r0), "=r"(r1), "=r"(r2), "=r"(r3) : "r"(addr));
}
__device__ __forceinline__ void ldm_x2(uint32_t& r0, uint32_t& r1, uint32_t addr) {
    asm volatile("ldmatrix.sync.aligned.m8n8.x2.shared.b16 {%0,%1}, [%2];"
                 : "=r"(r0), "=r"(r1) : "r"(addr));
}
__device__ __forceinline__ void ldm_x2t(uint32_t& r0, uint32_t& r1, uint32_t addr) {
    asm volatile("ldmatrix.sync.aligned.m8n8.x2.trans.shared.b16 {%0,%1}, [%2];"
                 : "=r"(r0), "=r"(r1) : "r"(addr));
}
__device__ __forceinline__ void mma16816(float* d, const uint32_t* a, const uint32_t* b) {
    asm volatile("mma.sync.aligned.m16n8k16.row.col.f32.bf16.bf16.f32 "
                 "{%0,%1,%2,%3}, {%4,%5,%6,%7}, {%8,%9}, {%0,%1,%2,%3};"
                 : "+f"(d[0]), "+f"(d[1]), "+f"(d[2]), "+f"(d[3])
                 : "r"(a[0]), "r"(a[1]), "r"(a[2]), "r"(a[3]), "r"(b[0]), "r"(b[1]));
}
__device__ __forceinline__ void split2(float x, float y, uint32_t& hi, uint32_t& lo) {
    __nv_bfloat16 hx = __float2bfloat16(x), hy = __float2bfloat16(y);
    __nv_bfloat162 h(hx, hy);
    __nv_bfloat162 l(__float2bfloat16(x - __bfloat162float(hx)),
                     __float2bfloat16(y - __bfloat162float(hy)));
    hi = *(uint32_t*)&h;
    lo = *(uint32_t*)&l;
}

// ---------------- fp32 -> bf16 hi/lo split (grid-stride) ----------------------
__global__ void cvt_split(const float* __restrict__ src,
                          __nv_bfloat16* __restrict__ hi,
                          __nv_bfloat16* __restrict__ lo, int n4)
{
    int i = blockIdx.x * blockDim.x + threadIdx.x;
    if (i >= n4) return;
    float4 v = ((const float4*)src)[i];
    uint32_t h0, l0, h1, l1;
    split2(v.x, v.y, h0, l0);
    split2(v.z, v.w, h1, l1);
    *(uint2*)(hi + (size_t)i * 4) = make_uint2(h0, h1);
    *(uint2*)(lo + (size_t)i * 4) = make_uint2(l0, l1);
}

// ---------------- GEMM (unchanged from R10) ------------------------------------
#define ROWB 80
#define GSTAGE 61440
#define GSM (2 * GSTAGE)

__global__ __launch_bounds__(256, 1) void gemm_bf(
    const __nv_bfloat16* __restrict__ Ah, const __nv_bfloat16* __restrict__ Al,
    const __nv_bfloat16* __restrict__ Bh, const __nv_bfloat16* __restrict__ Bl,
    float* __restrict__ C, int M, int N, int K)
{
    extern __shared__ __align__(128) char smem[];
    const uint32_t sb = smem_u32(smem);
    const int tid = threadIdx.x;
    const int lane = tid & 31, warp = tid >> 5;
    const int wm = warp >> 2, wn = warp & 3;
    const int bm = blockIdx.y * 128, bn = blockIdx.x * 256;
    const int NC = K / 32;

    const int ar = tid >> 2, ac = tid & 3;

    auto issue_stage = [&](int slot, int k0) {
        const uint32_t st = sb + slot * GSTAGE;
        {
            uint32_t d = st + ar * ROWB + ac * 16;
            const size_t s0 = (size_t)(bm + ar) * K + k0 + ac * 8;
            CP_ASYNC16(d,         Ah + s0);
            CP_ASYNC16(d + 10240, Al + s0);
            uint32_t d2 = st + (ar + 64) * ROWB + ac * 16;
            const size_t s2 = (size_t)(bm + ar + 64) * K + k0 + ac * 8;
            CP_ASYNC16(d2,         Ah + s2);
            CP_ASYNC16(d2 + 10240, Al + s2);
        }
#pragma unroll
        for (int i = 0; i < 4; i++) {
            int c = tid + i * 256;
            int br = c >> 2, bc = c & 3;
            uint32_t d = st + 20480 + br * ROWB + bc * 16;
            const size_t s0 = (size_t)(bn + br) * K + k0 + bc * 8;
            CP_ASYNC16(d,         Bh + s0);
            CP_ASYNC16(d + 20480, Bl + s0);
        }
    };

    issue_stage(0, 0);
    CP_COMMIT();

    float acc[32][4] = {};

    const uint32_t aoff = (uint32_t)((wm * 64 + (lane & 15)) * ROWB + (lane >> 4) * 16);
    const uint32_t boff = (uint32_t)(20480 + (wn * 64 + (lane & 7)) * ROWB +
                                     ((lane >> 3) & 1) * 16);

    for (int i = 0; i < NC; i++) {
        if (i > 0) __syncthreads();
        if (i + 1 < NC) { issue_stage((i + 1) & 1, (i + 1) * 32); CP_COMMIT(); CP_WAIT(1); }
        else           { CP_WAIT(0); }
        __syncthreads();

        const uint32_t st = sb + (i & 1) * GSTAGE;

#pragma unroll
        for (int kk = 0; kk < 2; kk++) {
            uint32_t ah[4][4], al[4][4];
#pragma unroll
            for (int am = 0; am < 4; am++) {
                uint32_t ad = st + aoff + am * 16 * ROWB + kk * 32;
                ldm_x4(ah[am][0], ah[am][1], ah[am][2], ah[am][3], ad);
                ldm_x4(al[am][0], al[am][1], al[am][2], al[am][3], ad + 10240);
            }
#pragma unroll
            for (int nt = 0; nt < 8; nt++) {
                uint32_t bh[2], bl[2];
                uint32_t bd = st + boff + nt * 8 * ROWB + kk * 32;
                ldm_x2(bh[0], bh[1], bd);
                ldm_x2(bl[0], bl[1], bd + 20480);
#pragma unroll
                for (int am = 0; am < 4; am++) {
                    mma16816(acc[am * 8 + nt], ah[am], bh);
                    mma16816(acc[am * 8 + nt], ah[am], bl);
                    mma16816(acc[am * 8 + nt], al[am], bh);
                }
            }
        }
    }

    const int er = bm + wm * 64 + (lane >> 2);
    const int ec = bn + wn * 64 + (lane & 3) * 2;
#pragma unroll
    for (int am = 0; am < 4; am++)
#pragma unroll
        for (int nt = 0; nt < 8; nt++) {
            float* d = acc[am * 8 + nt];
            int r = er + am * 16;
            int c = ec + nt * 8;
            *(float2*)(C + (size_t)r * N + c) = make_float2(d[0], d[1]);
            *(float2*)(C + (size_t)(r + 8) * N + c) = make_float2(d[2], d[3]);
        }
}

// ---------------- RoPE + split bf16 q/k/v + q0/k0 norms ----------------------
__global__ __launch_bounds__(256) void rope_split(const float* __restrict__ qkv,
                                                  const float* __restrict__ hyp)
{
    int bi = blockIdx.x * 8 + (threadIdx.x >> 5);
    int h = bi % H_;
    int t = (bi / H_) % T_;
    int b = bi / (H_ * T_);
    int j = threadIdx.x & 31;

    const float* src = qkv + (size_t)(b * T_ + t) * (3 * C_) + h * HD;
    float kc = hyp[h];

    float inv = powf(10000.0f, -(float)(2 * j) / 64.0f);
    float fr = (float)t * inv;
    float cs = cosf(fr);
    float sn = sinf(fr);

    size_t dst = ((size_t)(b * H_ + h) * T_ + t) * HD;

    float q1 = src[j], q2 = src[j + 32];
    float qo1 = q1 * cs + q2 * sn;
    float qo2 = -q1 * sn + q2 * cs;
    float k1 = src[C_ + j], k2 = src[C_ + j + 32];
    float ko1 = k1 * cs + k2 * sn;
    float ko2 = -k1 * sn + k2 * cs;
    float v1 = src[2 * C_ + j], v2 = src[2 * C_ + j + 32];

    __nv_bfloat16 hh;
    hh = __float2bfloat16(qo1); g_qh[dst + j] = hh;
    g_ql[dst + j] = __float2bfloat16(qo1 - __bfloat162float(hh));
    hh = __float2bfloat16(qo2); g_qh[dst + j + 32] = hh;
    g_ql[dst + j + 32] = __float2bfloat16(qo2 - __bfloat162float(hh));
    hh = __float2bfloat16(ko1); g_kh[dst + j] = hh;
    g_kl[dst + j] = __float2bfloat16(ko1 - __bfloat162float(hh));
    hh = __float2bfloat16(ko2); g_kh[dst + j + 32] = hh;
    g_kl[dst + j + 32] = __float2bfloat16(ko2 - __bfloat162float(hh));
    hh = __float2bfloat16(v1); g_vh[dst + j] = hh;
    g_vl[dst + j] = __float2bfloat16(v1 - __bfloat162float(hh));
    hh = __float2bfloat16(v2); g_vh[dst + j + 32] = hh;
    g_vl[dst + j + 32] = __float2bfloat16(v2 - __bfloat162float(hh));

    float sq = qo1 * qo1 + qo2 * qo2;
    float sk = ko1 * ko1 + ko2 * ko2;
#pragma unroll
    for (int off = 16; off; off >>= 1) {
        sq += __shfl_xor_sync(0xffffffffu, sq, off);
        sk += __shfl_xor_sync(0xffffffffu, sk, off);
    }
    if (j == 0) {
        size_t r = (size_t)(b * H_ + h) * T_ + t;
        g_q0[r] = sqrtf(kc + sq);
        g_k0[r] = sqrtf(kc + sk);
    }
}

// ---------------- score transform: 2 MUFU + FFMA-poly rcp/exp2 ---------------
// p = exp(min(1/(eps + sqrt(k)*acosh(arg)), 60))
// acosh(arg) = ln(arg + sqrt(arg^2-1)) = ln2 * lg2(y)
// rcp via bit-trick + 3 Newton; exp2 via magic-constant range-split + deg-4 poly.
__device__ __forceinline__ float score_p(float s, float q0, float k0,
                                         float invk, float c1) {
    float inner = s - q0 * k0;
    float arg = fmaxf(-inner * invk, 1.000001f);
    float t = fmaf(arg, arg, -1.0f);
    float sq; asm("sqrt.approx.f32 %0, %1;" : "=f"(sq) : "f"(t));      // MUFU 1
    float y = arg + sq;
    float lg; asm("lg2.approx.f32 %0, %1;" : "=f"(lg) : "f"(y));        // MUFU 2
    float u = fmaf(c1, lg, 1e-6f);           // eps + sqrt(k)*acosh(arg), u > 0

    // w = 1/u  (FFMA pipe: seed + 3 Newton)
    float r = __int_as_float(0x7EF311C3 - __float_as_int(u));
    r = r * (2.0f - u * r);
    r = r * (2.0f - u * r);
    r = r * (2.0f - u * r);

    // e2 = min(w, 60) * log2(e);  p = 2^e2   (e2 in [0, 86.56])
    float e2 = fminf(r, 60.0f) * 1.44269504f;
    float mgk = e2 + 12582912.0f;            // 2^23 * 1.5 : round-to-int capture
    int   n   = __float_as_int(mgk) - 0x4B400000;   // integer part
    float f   = e2 - (mgk - 12582912.0f);    // frac in [-0.5, 0.5]
    float pf  = fmaf(f, 0.0135557472f, 0.0520323690f);
    pf = fmaf(f, pf, 0.2413797743f);
    pf = fmaf(f, pf, 0.6931471825f);
    pf = fmaf(f, pf, 1.0f);                  // 2^f
    return __int_as_float(__float_as_int(pf) + (n << 23));
}

// ---------------- tensorized attention (layout unchanged from R10) ------------
#define AROWB 144
#define REG0 0
#define REG1 36864
#define SK0A 73728
#define ATT_SMEM 74240

__global__ __launch_bounds__(256, 2) void attn_mma(const float* __restrict__ hyp)
{
    extern __shared__ __align__(128) char smem[];
    const uint32_t sb = smem_u32(smem);
    const int tid = threadIdx.x;
    const int lane = tid & 31, warp = tid >> 5;
    const int qt = (int)gridDim.x - 1 - (int)blockIdx.x;
    const int h = blockIdx.y, b = blockIdx.z;
    const size_t bh = (size_t)b * H_ + h;
    const size_t qbase = (bh * T_ + (size_t)qt * 128) * HD;
    const size_t kvbase = bh * T_ * HD;
    const float* k0g = g_k0 + bh * T_;

    const float kc   = hyp[h];
    const float invk = 1.0f / kc;
    const float c1   = sqrtf(kc) * 0.69314718056f;

    const int ar0 = tid >> 3, ac0 = tid & 7;
    const int ar1 = (tid + 256) >> 3;

#pragma unroll
    for (int i = 0; i < 4; i++) {
        int ch = tid + i * 256;
        int row = ch >> 3, cc = ch & 7;
        uint32_t d = sb + REG0 + row * AROWB + cc * 16;
        CP_ASYNC16(d, g_qh + qbase + row * 64 + cc * 8);
        CP_ASYNC16(d + 18432, g_ql + qbase + row * 64 + cc * 8);
    }
    CP_COMMIT();

    auto issue_kv = [&](uint32_t reg, int st) {
        const uint32_t sk = sb + reg;
        const size_t tb = kvbase + (size_t)st * 64 * 64;
        uint32_t d0 = sk + ar0 * AROWB + ac0 * 16;
        const size_t s0 = tb + ar0 * 64 + ac0 * 8;
        CP_ASYNC16(d0,         g_kh + s0);
        CP_ASYNC16(d0 + 9216,  g_kl + s0);
        CP_ASYNC16(d0 + 18432, g_vh + s0);
        CP_ASYNC16(d0 + 27648, g_vl + s0);
        uint32_t d1 = sk + ar1 * AROWB + ac0 * 16;
        const size_t s1 = tb + ar1 * 64 + ac0 * 8;
        CP_ASYNC16(d1,         g_kh + s1);
        CP_ASYNC16(d1 + 9216,  g_kl + s1);
        CP_ASYNC16(d1 + 18432, g_vh + s1);
        CP_ASYNC16(d1 + 27648, g_vl + s1);
        if (tid < 16) CP_ASYNC16(sb + SK0A + (st & 1) * 256 + tid * 16,
                                 k0g + st * 64 + tid * 4);
    };

    const int ntile = 2 * qt + 2;
    issue_kv(REG1, 0);
    CP_COMMIT();

    CP_WAIT(1);
    __syncthreads();
    uint32_t qa_h[4][4], qa_l[4][4];
    const uint32_t qoff = (uint32_t)((warp * 16 + (lane & 15)) * AROWB + (lane >> 4) * 16);
#pragma unroll
    for (int g = 0; g < 4; g++) {
        ldm_x4(qa_h[g][0], qa_h[g][1], qa_h[g][2], qa_h[g][3], sb + REG0 + qoff + g * 32);
        ldm_x4(qa_l[g][0], qa_l[g][1], qa_l[g][2], qa_l[g][3], sb + REG0 + 18432 + qoff + g * 32);
    }

    const int r_in  = lane >> 2;
    const int cpair = (lane & 3) * 2;
    const int qr0 = qt * 128 + warp * 16 + r_in;
    const int qr1 = qr0 + 8;
    const float q00 = g_q0[bh * T_ + qr0];
    const float q01 = g_q0[bh * T_ + qr1];

    float O[8][4] = {};
    float ls0 = 0.0f, ls1 = 0.0f;

    for (int st = 0; st < ntile; st++) {
        __syncthreads();
        if (st + 1 < ntile) {
            issue_kv((st & 1) ? REG1 : REG0, st + 1);
            CP_COMMIT();
        }
        if (st + 1 < ntile) { CP_WAIT(1); } else { CP_WAIT(0); }
        __syncthreads();

        const uint32_t reg = (st & 1) ? REG0 : REG1;
        const uint32_t sKh = sb + reg;
        const uint32_t sKl = sKh + 9216;
        const uint32_t sVh = sKh + 18432;
        const uint32_t sVl = sKh + 27648;
        const uint32_t k0off = SK0A + (st & 1) * 256;

        const bool maskT = (st >= 2 * qt);
        const int key_base = st * 64;

        uint32_t pa_h[4][4], pa_l[4][4];

#pragma unroll
        for (int nt = 0; nt < 8; nt++) {
            float sacc[4] = {};
            const uint32_t kb = (uint32_t)((nt * 8 + (lane & 7)) * AROWB +
                                           ((lane >> 3) & 1) * 16);
#pragma unroll
            for (int g = 0; g < 4; g++) {
                uint32_t kh[2], kl[2];
                ldm_x2(kh[0], kh[1], sKh + kb + g * 32);
                ldm_x2(kl[0], kl[1], sKl + kb + g * 32);
                mma16816(sacc, qa_h[g], kh);
                mma16816(sacc, qa_h[g], kl);
                mma16816(sacc, qa_l[g], kh);
            }

            float2 k0p = *(const float2*)(smem + k0off + (nt * 8 + cpair) * 4);
            const int keyc = key_base + nt * 8 + cpair;

            float p0 = score_p(sacc[0], q00, k0p.x, invk, c1);
            float p1 = score_p(sacc[1], q00, k0p.y, invk, c1);
            float p2 = score_p(sacc[2], q01, k0p.x, invk, c1);
            float p3 = score_p(sacc[3], q01, k0p.y, invk, c1);
            if (maskT) {
                if (keyc     > qr0) p0 = 0.0f;
                if (keyc + 1 > qr0) p1 = 0.0f;
                if (keyc     > qr1) p2 = 0.0f;
                if (keyc + 1 > qr1) p3 = 0.0f;
            }
            ls0 += p0 + p1;
            ls1 += p2 + p3;

            const int g = nt >> 1;
            const int rb = (nt & 1) * 2;
            split2(p0, p1, pa_h[g][rb + 0], pa_l[g][rb + 0]);
            split2(p2, p3, pa_h[g][rb + 1], pa_l[g][rb + 1]);
        }

#pragma unroll
        for (int dt = 0; dt < 8; dt++) {
#pragma unroll
            for (int g = 0; g < 4; g++) {
                const uint32_t vo = (uint32_t)((g * 16 + (lane & 15)) * AROWB + dt * 16);
                uint32_t vh[2], vl[2];
                ldm_x2t(vh[0], vh[1], sVh + vo);
                ldm_x2t(vl[0], vl[1], sVl + vo);
                mma16816(O[dt], pa_h[g], vh);
                mma16816(O[dt], pa_h[g], vl);
                mma16816(O[dt], pa_l[g], vh);
            }
        }
    }

    ls0 += __shfl_xor_sync(0xffffffffu, ls0, 1);
    ls0 += __shfl_xor_sync(0xffffffffu, ls0, 2);
    ls1 += __shfl_xor_sync(0xffffffffu, ls1, 1);
    ls1 += __shfl_xor_sync(0xffffffffu, ls1, 2);
    const float n0 = 1.0f / ls0;
    const float n1 = 1.0f / ls1;

    const size_t o0 = ((size_t)b * T_ + qr0) * C_ + h * 64;
    const size_t o1 = ((size_t)b * T_ + qr1) * C_ + h * 64;
#pragma unroll
    for (int dt = 0; dt < 8; dt++) {
        const int c = dt * 8 + cpair;
        uint32_t hh, ll;
        split2(O[dt][0] * n0, O[dt][1] * n0, hh, ll);
        *(uint32_t*)(g_oh + o0 + c) = hh;
        *(uint32_t*)(g_ol + o0 + c) = ll;
        split2(O[dt][2] * n1, O[dt][3] * n1, hh, ll);
        *(uint32_t*)(g_oh + o1 + c) = hh;
        *(uint32_t*)(g_ol + o1 + c) = ll;
    }
}

// ---------------- launch ------------------------------------------------------
extern "C" void kernel_launch(void* const* d_in, const int* in_sizes, int n_in,
                              void* d_out, int out_size)
{
    const float* x    = (const float*)d_in[0];
    const float* Wqkv = (const float*)d_in[1];
    const float* Wout = (const float*)d_in[2];
    const float* hyp  = (const float*)d_in[3];
    float* out = (float*)d_out;

    static float* p_qkv = nullptr;
    static __nv_bfloat16 *p_xh, *p_xl, *p_w1h, *p_w1l, *p_w2h, *p_w2l, *p_oh, *p_ol;
    if (!p_qkv) {
        cudaGetSymbolAddress((void**)&p_qkv, g_qkv);
        cudaGetSymbolAddress((void**)&p_xh, g_xh);
        cudaGetSymbolAddress((void**)&p_xl, g_xl);
        cudaGetSymbolAddress((void**)&p_w1h, g_w1h);
        cudaGetSymbolAddress((void**)&p_w1l, g_w1l);
        cudaGetSymbolAddress((void**)&p_w2h, g_w2h);
        cudaGetSymbolAddress((void**)&p_w2l, g_w2l);
        cudaGetSymbolAddress((void**)&p_oh, g_oh);
        cudaGetSymbolAddress((void**)&p_ol, g_ol);
        cudaFuncSetAttribute(gemm_bf,
                             cudaFuncAttributeMaxDynamicSharedMemorySize, GSM);
        cudaFuncSetAttribute(attn_mma,
                             cudaFuncAttributeMaxDynamicSharedMemorySize, ATT_SMEM);
    }

    // 0) split conversions
    cvt_split<<<(4096 * 1024 / 4 + 255) / 256, 256>>>(x, p_xh, p_xl, 4096 * 1024 / 4);
    cvt_split<<<(3072 * 1024 / 4 + 255) / 256, 256>>>(Wqkv, p_w1h, p_w1l, 3072 * 1024 / 4);
    cvt_split<<<(1024 * 1024 / 4 + 255) / 256, 256>>>(Wout, p_w2h, p_w2l, 1024 * 1024 / 4);

    // 1) qkv = x @ W_qkv^T
    gemm_bf<<<dim3(3072 / 256, 4096 / 128), 256, GSM>>>(
        p_xh, p_xl, p_w1h, p_w1l, p_qkv, 4096, 3072, 1024);

    // 2) RoPE + split + norms
    rope_split<<<B_ * T_ * H_ / 8, 256>>>(p_qkv, hyp);

    // 3) tensorized attention
    attn_mma<<<dim3(T_ / 128, H_, B_), 256, ATT_SMEM>>>(hyp);

    // 4) out = o @ W_out^T
    gemm_bf<<<dim3(1024 / 256, 4096 / 128), 256, GSM>>>(
        p_oh, p_ol, p_w2h, p_w2l, out, 4096, 1024, 1024);
}

// round 12
// speedup vs baseline: 1.0184x; 1.0184x over previous
#include <cuda_runtime.h>
#include <cuda_bf16.h>
#include <math.h>
#include <stdint.h>

#define B_ 4
#define T_ 1024
#define C_ 1024
#define H_ 16
#define HD 64

// ---------------- scratch (static device globals; no allocation) -------------
__device__ __align__(16) float g_qkv[(size_t)4096 * 3072];
__device__ float g_q0[(size_t)B_ * H_ * T_];
__device__ float g_k0[(size_t)B_ * H_ * T_];
__device__ __align__(16) __nv_bfloat16 g_xh[(size_t)4096 * 1024];
__device__ __align__(16) __nv_bfloat16 g_xl[(size_t)4096 * 1024];
__device__ __align__(16) __nv_bfloat16 g_w1h[(size_t)3072 * 1024];
__device__ __align__(16) __nv_bfloat16 g_w1l[(size_t)3072 * 1024];
__device__ __align__(16) __nv_bfloat16 g_w2h[(size_t)1024 * 1024];
__device__ __align__(16) __nv_bfloat16 g_w2l[(size_t)1024 * 1024];
__device__ __align__(16) __nv_bfloat16 g_qh[(size_t)4096 * 1024];
__device__ __align__(16) __nv_bfloat16 g_ql[(size_t)4096 * 1024];
__device__ __align__(16) __nv_bfloat16 g_kh[(size_t)4096 * 1024];
__device__ __align__(16) __nv_bfloat16 g_kl[(size_t)4096 * 1024];
__device__ __align__(16) __nv_bfloat16 g_vh[(size_t)4096 * 1024];
__device__ __align__(16) __nv_bfloat16 g_vl[(size_t)4096 * 1024];
__device__ __align__(16) __nv_bfloat16 g_oh[(size_t)4096 * 1024];
__device__ __align__(16) __nv_bfloat16 g_ol[(size_t)4096 * 1024];

// ---------------- helpers ------------------------------------------------------
__device__ __forceinline__ uint32_t smem_u32(const void* p) {
    uint32_t a;
    asm("{ .reg .u64 t; cvta.to.shared.u64 t, %1; cvt.u32.u64 %0, t; }" : "=r"(a) : "l"(p));
    return a;
}
#define CP_ASYNC16(d, s)  asm volatile("cp.async.cg.shared.global [%0], [%1], 16;" :: "r"(d), "l"(s))
#define CP_COMMIT()       asm volatile("cp.async.commit_group;" ::: "memory")
#define CP_WAIT(n)        asm volatile("cp.async.wait_group %0;" :: "n"(n) : "memory")

__device__ __forceinline__ void ldm_x4(uint32_t& r0, uint32_t& r1, uint32_t& r2, uint32_t& r3,
                                       uint32_t addr) {
    asm volatile("ldmatrix.sync.aligned.m8n8.x4.shared.b16 {%0,%1,%2,%3}, [%4];"
                 : "=r"(r0), "=r"(r1), "=r"(r2), "=r"(r3) : "r"(addr));
}
__device__ __forceinline__ void ldm_x2(uint32_t& r0, uint32_t& r1, uint32_t addr) {
    asm volatile("ldmatrix.sync.aligned.m8n8.x2.shared.b16 {%0,%1}, [%2];"
                 : "=r"(r0), "=r"(r1) : "r"(addr));
}
__device__ __forceinline__ void ldm_x2t(uint32_t& r0, uint32_t& r1, uint32_t addr) {
    asm volatile("ldmatrix.sync.aligned.m8n8.x2.trans.shared.b16 {%0,%1}, [%2];"
                 : "=r"(r0), "=r"(r1) : "r"(addr));
}
__device__ __forceinline__ void mma16816(float* d, const uint32_t* a, const uint32_t* b) {
    asm volatile("mma.sync.aligned.m16n8k16.row.col.f32.bf16.bf16.f32 "
                 "{%0,%1,%2,%3}, {%4,%5,%6,%7}, {%8,%9}, {%0,%1,%2,%3};"
                 : "+f"(d[0]), "+f"(d[1]), "+f"(d[2]), "+f"(d[3])
                 : "r"(a[0]), "r"(a[1]), "r"(a[2]), "r"(a[3]), "r"(b[0]), "r"(b[1]));
}
__device__ __forceinline__ void split2(float x, float y, uint32_t& hi, uint32_t& lo) {
    __nv_bfloat16 hx = __float2bfloat16(x), hy = __float2bfloat16(y);
    __nv_bfloat162 h(hx, hy);
    __nv_bfloat162 l(__float2bfloat16(x - __bfloat162float(hx)),
                     __float2bfloat16(y - __bfloat162float(hy)));
    hi = *(uint32_t*)&h;
    lo = *(uint32_t*)&l;
}

// ---------------- fp32 -> bf16 hi/lo split (grid-stride) ----------------------
__global__ void cvt_split(const float* __restrict__ src,
                          __nv_bfloat16* __restrict__ hi,
                          __nv_bfloat16* __restrict__ lo, int n4)
{
    int i = blockIdx.x * blockDim.x + threadIdx.x;
    if (i >= n4) return;
    float4 v = ((const float4*)src)[i];
    uint32_t h0, l0, h1, l1;
    split2(v.x, v.y, h0, l0);
    split2(v.z, v.w, h1, l1);
    *(uint2*)(hi + (size_t)i * 4) = make_uint2(h0, h1);
    *(uint2*)(lo + (size_t)i * 4) = make_uint2(l0, l1);
}

// ---------------- GEMM: pass-major MMA ordering (32-wide indep chains) --------
#define ROWB 80
#define GSTAGE 61440
#define GSM (2 * GSTAGE)

__global__ __launch_bounds__(256, 1) void gemm_bf(
    const __nv_bfloat16* __restrict__ Ah, const __nv_bfloat16* __restrict__ Al,
    const __nv_bfloat16* __restrict__ Bh, const __nv_bfloat16* __restrict__ Bl,
    float* __restrict__ C, int M, int N, int K)
{
    extern __shared__ __align__(128) char smem[];
    const uint32_t sb = smem_u32(smem);
    const int tid = threadIdx.x;
    const int lane = tid & 31, warp = tid >> 5;
    const int wm = warp >> 2, wn = warp & 3;
    const int bm = blockIdx.y * 128, bn = blockIdx.x * 256;
    const int NC = K / 32;

    const int ar = tid >> 2, ac = tid & 3;

    auto issue_stage = [&](int slot, int k0) {
        const uint32_t st = sb + slot * GSTAGE;
        {
            uint32_t d = st + ar * ROWB + ac * 16;
            const size_t s0 = (size_t)(bm + ar) * K + k0 + ac * 8;
            CP_ASYNC16(d,         Ah + s0);
            CP_ASYNC16(d + 10240, Al + s0);
            uint32_t d2 = st + (ar + 64) * ROWB + ac * 16;
            const size_t s2 = (size_t)(bm + ar + 64) * K + k0 + ac * 8;
            CP_ASYNC16(d2,         Ah + s2);
            CP_ASYNC16(d2 + 10240, Al + s2);
        }
#pragma unroll
        for (int i = 0; i < 4; i++) {
            int c = tid + i * 256;
            int br = c >> 2, bc = c & 3;
            uint32_t d = st + 20480 + br * ROWB + bc * 16;
            const size_t s0 = (size_t)(bn + br) * K + k0 + bc * 8;
            CP_ASYNC16(d,         Bh + s0);
            CP_ASYNC16(d + 20480, Bl + s0);
        }
    };

    issue_stage(0, 0);
    CP_COMMIT();

    float acc[32][4] = {};

    const uint32_t aoff = (uint32_t)((wm * 64 + (lane & 15)) * ROWB + (lane >> 4) * 16);
    const uint32_t boff = (uint32_t)(20480 + (wn * 64 + (lane & 7)) * ROWB +
                                     ((lane >> 3) & 1) * 16);

    for (int i = 0; i < NC; i++) {
        if (i > 0) __syncthreads();
        if (i + 1 < NC) { issue_stage((i + 1) & 1, (i + 1) * 32); CP_COMMIT(); CP_WAIT(1); }
        else           { CP_WAIT(0); }
        __syncthreads();

        const uint32_t st = sb + (i & 1) * GSTAGE;

#pragma unroll
        for (int kk = 0; kk < 2; kk++) {
            uint32_t ah[4][4], al[4][4], bh[8][2], bl[8][2];
#pragma unroll
            for (int am = 0; am < 4; am++) {
                uint32_t ad = st + aoff + am * 16 * ROWB + kk * 32;
                ldm_x4(ah[am][0], ah[am][1], ah[am][2], ah[am][3], ad);
                ldm_x4(al[am][0], al[am][1], al[am][2], al[am][3], ad + 10240);
            }
#pragma unroll
            for (int nt = 0; nt < 8; nt++) {
                uint32_t bd = st + boff + nt * 8 * ROWB + kk * 32;
                ldm_x2(bh[nt][0], bh[nt][1], bd);
                ldm_x2(bl[nt][0], bl[nt][1], bd + 20480);
            }
            // pass-major: 32 independent MMAs per pass; same-acc distance = 32
#pragma unroll
            for (int am = 0; am < 4; am++)
#pragma unroll
                for (int nt = 0; nt < 8; nt++)
                    mma16816(acc[am * 8 + nt], ah[am], bh[nt]);
#pragma unroll
            for (int am = 0; am < 4; am++)
#pragma unroll
                for (int nt = 0; nt < 8; nt++)
                    mma16816(acc[am * 8 + nt], ah[am], bl[nt]);
#pragma unroll
            for (int am = 0; am < 4; am++)
#pragma unroll
                for (int nt = 0; nt < 8; nt++)
                    mma16816(acc[am * 8 + nt], al[am], bh[nt]);
        }
    }

    const int er = bm + wm * 64 + (lane >> 2);
    const int ec = bn + wn * 64 + (lane & 3) * 2;
#pragma unroll
    for (int am = 0; am < 4; am++)
#pragma unroll
        for (int nt = 0; nt < 8; nt++) {
            float* d = acc[am * 8 + nt];
            int r = er + am * 16;
            int c = ec + nt * 8;
            *(float2*)(C + (size_t)r * N + c) = make_float2(d[0], d[1]);
            *(float2*)(C + (size_t)(r + 8) * N + c) = make_float2(d[2], d[3]);
        }
}

// ---------------- RoPE + split bf16 q/k/v + q0/k0 norms ----------------------
__global__ __launch_bounds__(256) void rope_split(const float* __restrict__ qkv,
                                                  const float* __restrict__ hyp)
{
    int bi = blockIdx.x * 8 + (threadIdx.x >> 5);
    int h = bi % H_;
    int t = (bi / H_) % T_;
    int b = bi / (H_ * T_);
    int j = threadIdx.x & 31;

    const float* src = qkv + (size_t)(b * T_ + t) * (3 * C_) + h * HD;
    float kc = hyp[h];

    float inv = powf(10000.0f, -(float)(2 * j) / 64.0f);
    float fr = (float)t * inv;
    float cs = cosf(fr);
    float sn = sinf(fr);

    size_t dst = ((size_t)(b * H_ + h) * T_ + t) * HD;

    float q1 = src[j], q2 = src[j + 32];
    float qo1 = q1 * cs + q2 * sn;
    float qo2 = -q1 * sn + q2 * cs;
    float k1 = src[C_ + j], k2 = src[C_ + j + 32];
    float ko1 = k1 * cs + k2 * sn;
    float ko2 = -k1 * sn + k2 * cs;
    float v1 = src[2 * C_ + j], v2 = src[2 * C_ + j + 32];

    __nv_bfloat16 hh;
    hh = __float2bfloat16(qo1); g_qh[dst + j] = hh;
    g_ql[dst + j] = __float2bfloat16(qo1 - __bfloat162float(hh));
    hh = __float2bfloat16(qo2); g_qh[dst + j + 32] = hh;
    g_ql[dst + j + 32] = __float2bfloat16(qo2 - __bfloat162float(hh));
    hh = __float2bfloat16(ko1); g_kh[dst + j] = hh;
    g_kl[dst + j] = __float2bfloat16(ko1 - __bfloat162float(hh));
    hh = __float2bfloat16(ko2); g_kh[dst + j + 32] = hh;
    g_kl[dst + j + 32] = __float2bfloat16(ko2 - __bfloat162float(hh));
    hh = __float2bfloat16(v1); g_vh[dst + j] = hh;
    g_vl[dst + j] = __float2bfloat16(v1 - __bfloat162float(hh));
    hh = __float2bfloat16(v2); g_vh[dst + j + 32] = hh;
    g_vl[dst + j + 32] = __float2bfloat16(v2 - __bfloat162float(hh));

    float sq = qo1 * qo1 + qo2 * qo2;
    float sk = ko1 * ko1 + ko2 * ko2;
#pragma unroll
    for (int off = 16; off; off >>= 1) {
        sq += __shfl_xor_sync(0xffffffffu, sq, off);
        sk += __shfl_xor_sync(0xffffffffu, sk, off);
    }
    if (j == 0) {
        size_t r = (size_t)(b * H_ + h) * T_ + t;
        g_q0[r] = sqrtf(kc + sq);
        g_k0[r] = sqrtf(kc + sk);
    }
}

// ---------------- per-score hyperbolic transform (4 MUFU, R10 version) --------
__device__ __forceinline__ float score_p(float s, float q0, float k0,
                                         float invk, float c1) {
    float inner = s - q0 * k0;
    float arg = fmaxf(-inner * invk, 1.000001f);
    float t = fmaf(arg, arg, -1.0f);
    float sq; asm("sqrt.approx.f32 %0, %1;" : "=f"(sq) : "f"(t));
    float y = arg + sq;
    float lg; asm("lg2.approx.f32 %0, %1;" : "=f"(lg) : "f"(y));
    float u = fmaf(c1, lg, 1e-6f);
    float w; asm("rcp.approx.f32 %0, %1;" : "=f"(w) : "f"(u));
    w = fminf(w, 60.0f);
    float p; asm("ex2.approx.f32 %0, %1;" : "=f"(p) : "f"(w * 1.44269504f));
    return p;
}

// ---------------- tensorized attention, pass-major MMA ordering ---------------
#define AROWB 144
#define REG0 0
#define REG1 36864
#define SK0A 73728
#define ATT_SMEM 74240

__global__ __launch_bounds__(256, 1) void attn_mma(const float* __restrict__ hyp)
{
    extern __shared__ __align__(128) char smem[];
    const uint32_t sb = smem_u32(smem);
    const int tid = threadIdx.x;
    const int lane = tid & 31, warp = tid >> 5;
    const int qt = (int)gridDim.x - 1 - (int)blockIdx.x;
    const int h = blockIdx.y, b = blockIdx.z;
    const size_t bh = (size_t)b * H_ + h;
    const size_t qbase = (bh * T_ + (size_t)qt * 128) * HD;
    const size_t kvbase = bh * T_ * HD;
    const float* k0g = g_k0 + bh * T_;

    const float kc   = hyp[h];
    const float invk = 1.0f / kc;
    const float c1   = sqrtf(kc) * 0.69314718056f;

    const int ar0 = tid >> 3, ac0 = tid & 7;
    const int ar1 = (tid + 256) >> 3;

#pragma unroll
    for (int i = 0; i < 4; i++) {
        int ch = tid + i * 256;
        int row = ch >> 3, cc = ch & 7;
        uint32_t d = sb + REG0 + row * AROWB + cc * 16;
        CP_ASYNC16(d, g_qh + qbase + row * 64 + cc * 8);
        CP_ASYNC16(d + 18432, g_ql + qbase + row * 64 + cc * 8);
    }
    CP_COMMIT();

    auto issue_kv = [&](uint32_t reg, int st) {
        const uint32_t sk = sb + reg;
        const size_t tb = kvbase + (size_t)st * 64 * 64;
        uint32_t d0 = sk + ar0 * AROWB + ac0 * 16;
        const size_t s0 = tb + ar0 * 64 + ac0 * 8;
        CP_ASYNC16(d0,         g_kh + s0);
        CP_ASYNC16(d0 + 9216,  g_kl + s0);
        CP_ASYNC16(d0 + 18432, g_vh + s0);
        CP_ASYNC16(d0 + 27648, g_vl + s0);
        uint32_t d1 = sk + ar1 * AROWB + ac0 * 16;
        const size_t s1 = tb + ar1 * 64 + ac0 * 8;
        CP_ASYNC16(d1,         g_kh + s1);
        CP_ASYNC16(d1 + 9216,  g_kl + s1);
        CP_ASYNC16(d1 + 18432, g_vh + s1);
        CP_ASYNC16(d1 + 27648, g_vl + s1);
        if (tid < 16) CP_ASYNC16(sb + SK0A + (st & 1) * 256 + tid * 16,
                                 k0g + st * 64 + tid * 4);
    };

    const int ntile = 2 * qt + 2;
    issue_kv(REG1, 0);
    CP_COMMIT();

    CP_WAIT(1);
    __syncthreads();
    uint32_t qa_h[4][4], qa_l[4][4];
    const uint32_t qoff = (uint32_t)((warp * 16 + (lane & 15)) * AROWB + (lane >> 4) * 16);
#pragma unroll
    for (int g = 0; g < 4; g++) {
        ldm_x4(qa_h[g][0], qa_h[g][1], qa_h[g][2], qa_h[g][3], sb + REG0 + qoff + g * 32);
        ldm_x4(qa_l[g][0], qa_l[g][1], qa_l[g][2], qa_l[g][3], sb + REG0 + 18432 + qoff + g * 32);
    }

    const int r_in  = lane >> 2;
    const int cpair = (lane & 3) * 2;
    const int qr0 = qt * 128 + warp * 16 + r_in;
    const int qr1 = qr0 + 8;
    const float q00 = g_q0[bh * T_ + qr0];
    const float q01 = g_q0[bh * T_ + qr1];

    float O[8][4] = {};
    float ls0 = 0.0f, ls1 = 0.0f;

    const uint32_t kfb = (uint32_t)((lane & 7) * AROWB + ((lane >> 3) & 1) * 16);
    const uint32_t vfb = (uint32_t)((lane & 15) * AROWB);

    for (int st = 0; st < ntile; st++) {
        __syncthreads();
        if (st + 1 < ntile) {
            issue_kv((st & 1) ? REG1 : REG0, st + 1);
            CP_COMMIT();
        }
        if (st + 1 < ntile) { CP_WAIT(1); } else { CP_WAIT(0); }
        __syncthreads();

        const uint32_t reg = (st & 1) ? REG0 : REG1;
        const uint32_t sKh = sb + reg;
        const uint32_t sKl = sKh + 9216;
        const uint32_t sVh = sKh + 18432;
        const uint32_t sVl = sKh + 27648;
        const uint32_t k0off = SK0A + (st & 1) * 256;

        const bool maskT = (st >= 2 * qt);
        const int key_base = st * 64;

        // ---- S = Q K^T  (pass-major; kf buffer reused for kh then kl)
        float sacc[8][4] = {};
#pragma unroll
        for (int g = 0; g < 4; g++) {
            uint32_t kf[8][2];
#pragma unroll
            for (int nt = 0; nt < 8; nt++)
                ldm_x2(kf[nt][0], kf[nt][1], sKh + kfb + nt * 8 * AROWB + g * 32);
#pragma unroll
            for (int nt = 0; nt < 8; nt++) mma16816(sacc[nt], qa_h[g], kf[nt]);
#pragma unroll
            for (int nt = 0; nt < 8; nt++) mma16816(sacc[nt], qa_l[g], kf[nt]);
#pragma unroll
            for (int nt = 0; nt < 8; nt++)
                ldm_x2(kf[nt][0], kf[nt][1], sKl + kfb + nt * 8 * AROWB + g * 32);
#pragma unroll
            for (int nt = 0; nt < 8; nt++) mma16816(sacc[nt], qa_h[g], kf[nt]);
        }

        // ---- transform + pack P
        uint32_t pa_h[4][4], pa_l[4][4];
#pragma unroll
        for (int nt = 0; nt < 8; nt++) {
            float2 k0p = *(const float2*)(smem + k0off + (nt * 8 + cpair) * 4);
            const int keyc = key_base + nt * 8 + cpair;

            float p0 = score_p(sacc[nt][0], q00, k0p.x, invk, c1);
            float p1 = score_p(sacc[nt][1], q00, k0p.y, invk, c1);
            float p2 = score_p(sacc[nt][2], q01, k0p.x, invk, c1);
            float p3 = score_p(sacc[nt][3], q01, k0p.y, invk, c1);
            if (maskT) {
                if (keyc     > qr0) p0 = 0.0f;
                if (keyc + 1 > qr0) p1 = 0.0f;
                if (keyc     > qr1) p2 = 0.0f;
                if (keyc + 1 > qr1) p3 = 0.0f;
            }
            ls0 += p0 + p1;
            ls1 += p2 + p3;

            const int g = nt >> 1;
            const int rb = (nt & 1) * 2;
            split2(p0, p1, pa_h[g][rb + 0], pa_l[g][rb + 0]);
            split2(p2, p3, pa_h[g][rb + 1], pa_l[g][rb + 1]);
        }

        // ---- O += P V  (pass-major; vf buffer reused for vh then vl)
#pragma unroll
        for (int g = 0; g < 4; g++) {
            uint32_t vf[8][2];
#pragma unroll
            for (int dt = 0; dt < 8; dt++)
                ldm_x2t(vf[dt][0], vf[dt][1], sVh + vfb + g * 16 * AROWB + dt * 16);
#pragma unroll
            for (int dt = 0; dt < 8; dt++) mma16816(O[dt], pa_h[g], vf[dt]);
#pragma unroll
            for (int dt = 0; dt < 8; dt++) mma16816(O[dt], pa_l[g], vf[dt]);
#pragma unroll
            for (int dt = 0; dt < 8; dt++)
                ldm_x2t(vf[dt][0], vf[dt][1], sVl + vfb + g * 16 * AROWB + dt * 16);
#pragma unroll
            for (int dt = 0; dt < 8; dt++) mma16816(O[dt], pa_h[g], vf[dt]);
        }
    }

    ls0 += __shfl_xor_sync(0xffffffffu, ls0, 1);
    ls0 += __shfl_xor_sync(0xffffffffu, ls0, 2);
    ls1 += __shfl_xor_sync(0xffffffffu, ls1, 1);
    ls1 += __shfl_xor_sync(0xffffffffu, ls1, 2);
    const float n0 = 1.0f / ls0;
    const float n1 = 1.0f / ls1;

    const size_t o0 = ((size_t)b * T_ + qr0) * C_ + h * 64;
    const size_t o1 = ((size_t)b * T_ + qr1) * C_ + h * 64;
#pragma unroll
    for (int dt = 0; dt < 8; dt++) {
        const int c = dt * 8 + cpair;
        uint32_t hh, ll;
        split2(O[dt][0] * n0, O[dt][1] * n0, hh, ll);
        *(uint32_t*)(g_oh + o0 + c) = hh;
        *(uint32_t*)(g_ol + o0 + c) = ll;
        split2(O[dt][2] * n1, O[dt][3] * n1, hh, ll);
        *(uint32_t*)(g_oh + o1 + c) = hh;
        *(uint32_t*)(g_ol + o1 + c) = ll;
    }
}

// ---------------- launch ------------------------------------------------------
extern "C" void kernel_launch(void* const* d_in, const int* in_sizes, int n_in,
                              void* d_out, int out_size)
{
    const float* x    = (const float*)d_in[0];
    const float* Wqkv = (const float*)d_in[1];
    const float* Wout = (const float*)d_in[2];
    const float* hyp  = (const float*)d_in[3];
    float* out = (float*)d_out;

    static float* p_qkv = nullptr;
    static __nv_bfloat16 *p_xh, *p_xl, *p_w1h, *p_w1l, *p_w2h, *p_w2l, *p_oh, *p_ol;
    if (!p_qkv) {
        cudaGetSymbolAddress((void**)&p_qkv, g_qkv);
        cudaGetSymbolAddress((void**)&p_xh, g_xh);
        cudaGetSymbolAddress((void**)&p_xl, g_xl);
        cudaGetSymbolAddress((void**)&p_w1h, g_w1h);
        cudaGetSymbolAddress((void**)&p_w1l, g_w1l);
        cudaGetSymbolAddress((void**)&p_w2h, g_w2h);
        cudaGetSymbolAddress((void**)&p_w2l, g_w2l);
        cudaGetSymbolAddress((void**)&p_oh, g_oh);
        cudaGetSymbolAddress((void**)&p_ol, g_ol);
        cudaFuncSetAttribute(gemm_bf,
                             cudaFuncAttributeMaxDynamicSharedMemorySize, GSM);
        cudaFuncSetAttribute(attn_mma,
                             cudaFuncAttributeMaxDynamicSharedMemorySize, ATT_SMEM);
    }

    // 0) split conversions
    cvt_split<<<(4096 * 1024 / 4 + 255) / 256, 256>>>(x, p_xh, p_xl, 4096 * 1024 / 4);
    cvt_split<<<(3072 * 1024 / 4 + 255) / 256, 256>>>(Wqkv, p_w1h, p_w1l, 3072 * 1024 / 4);
    cvt_split<<<(1024 * 1024 / 4 + 255) / 256, 256>>>(Wout, p_w2h, p_w2l, 1024 * 1024 / 4);

    // 1) qkv = x @ W_qkv^T
    gemm_bf<<<dim3(3072 / 256, 4096 / 128), 256, GSM>>>(
        p_xh, p_xl, p_w1h, p_w1l, p_qkv, 4096, 3072, 1024);

    // 2) RoPE + split + norms
    rope_split<<<B_ * T_ * H_ / 8, 256>>>(p_qkv, hyp);

    // 3) tensorized attention
    attn_mma<<<dim3(T_ / 128, H_, B_), 256, ATT_SMEM>>>(hyp);

    // 4) out = o @ W_out^T
    gemm_bf<<<dim3(1024 / 256, 4096 / 128), 256, GSM>>>(
        p_oh, p_ol, p_w2h, p_w2l, out, 4096, 1024, 1024);
}

// round 13
// speedup vs baseline: 1.2488x; 1.2262x over previous
#include <cuda_runtime.h>
#include <cuda_bf16.h>
#include <cuda_fp16.h>
#include <math.h>
#include <stdint.h>

#define B_ 4
#define T_ 1024
#define C_ 1024
#define H_ 16
#define HD 64

// ---------------- scratch (static device globals; no allocation) -------------
__device__ __align__(16) float g_qkv[(size_t)4096 * 3072];
__device__ float g_q0[(size_t)B_ * H_ * T_];
__device__ float g_k0[(size_t)B_ * H_ * T_];
// fp16 split operands for the projection GEMMs
__device__ __align__(16) __half g_xh[(size_t)4096 * 1024];
__device__ __align__(16) __half g_xl[(size_t)4096 * 1024];
__device__ __align__(16) __half g_w1h[(size_t)3072 * 1024];
__device__ __align__(16) __half g_w2h[(size_t)1024 * 1024];
__device__ __align__(16) __half g_oh[(size_t)4096 * 1024];
__device__ __align__(16) __half g_ol[(size_t)4096 * 1024];
// bf16 split q/k/v for attention (3-pass path, unchanged)
__device__ __align__(16) __nv_bfloat16 g_qh[(size_t)4096 * 1024];
__device__ __align__(16) __nv_bfloat16 g_ql[(size_t)4096 * 1024];
__device__ __align__(16) __nv_bfloat16 g_kh[(size_t)4096 * 1024];
__device__ __align__(16) __nv_bfloat16 g_kl[(size_t)4096 * 1024];
__device__ __align__(16) __nv_bfloat16 g_vh[(size_t)4096 * 1024];
__device__ __align__(16) __nv_bfloat16 g_vl[(size_t)4096 * 1024];

// ---------------- helpers ------------------------------------------------------
__device__ __forceinline__ uint32_t smem_u32(const void* p) {
    uint32_t a;
    asm("{ .reg .u64 t; cvta.to.shared.u64 t, %1; cvt.u32.u64 %0, t; }" : "=r"(a) : "l"(p));
    return a;
}
#define CP_ASYNC16(d, s)  asm volatile("cp.async.cg.shared.global [%0], [%1], 16;" :: "r"(d), "l"(s))
#define CP_COMMIT()       asm volatile("cp.async.commit_group;" ::: "memory")
#define CP_WAIT(n)        asm volatile("cp.async.wait_group %0;" :: "n"(n) : "memory")

__device__ __forceinline__ void ldm_x4(uint32_t& r0, uint32_t& r1, uint32_t& r2, uint32_t& r3,
                                       uint32_t addr) {
    asm volatile("ldmatrix.sync.aligned.m8n8.x4.shared.b16 {%0,%1,%2,%3}, [%4];"
                 : "=r"(r0), "=r"(r1), "=r"(r2), "=r"(r3) : "r"(addr));
}
__device__ __forceinline__ void ldm_x2(uint32_t& r0, uint32_t& r1, uint32_t addr) {
    asm volatile("ldmatrix.sync.aligned.m8n8.x2.shared.b16 {%0,%1}, [%2];"
                 : "=r"(r0), "=r"(r1) : "r"(addr));
}
__device__ __forceinline__ void ldm_x2t(uint32_t& r0, uint32_t& r1, uint32_t addr) {
    asm volatile("ldmatrix.sync.aligned.m8n8.x2.trans.shared.b16 {%0,%1}, [%2];"
                 : "=r"(r0), "=r"(r1) : "r"(addr));
}
// bf16 mma (attention)
__device__ __forceinline__ void mma16816(float* d, const uint32_t* a, const uint32_t* b) {
    asm volatile("mma.sync.aligned.m16n8k16.row.col.f32.bf16.bf16.f32 "
                 "{%0,%1,%2,%3}, {%4,%5,%6,%7}, {%8,%9}, {%0,%1,%2,%3};"
                 : "+f"(d[0]), "+f"(d[1]), "+f"(d[2]), "+f"(d[3])
                 : "r"(a[0]), "r"(a[1]), "r"(a[2]), "r"(a[3]), "r"(b[0]), "r"(b[1]));
}
// fp16 mma (projection GEMMs)
__device__ __forceinline__ void mma16816h(float* d, const uint32_t* a, const uint32_t* b) {
    asm volatile("mma.sync.aligned.m16n8k16.row.col.f32.f16.f16.f32 "
                 "{%0,%1,%2,%3}, {%4,%5,%6,%7}, {%8,%9}, {%0,%1,%2,%3};"
                 : "+f"(d[0]), "+f"(d[1]), "+f"(d[2]), "+f"(d[3])
                 : "r"(a[0]), "r"(a[1]), "r"(a[2]), "r"(a[3]), "r"(b[0]), "r"(b[1]));
}
__device__ __forceinline__ void split2(float x, float y, uint32_t& hi, uint32_t& lo) {
    __nv_bfloat16 hx = __float2bfloat16(x), hy = __float2bfloat16(y);
    __nv_bfloat162 h(hx, hy);
    __nv_bfloat162 l(__float2bfloat16(x - __bfloat162float(hx)),
                     __float2bfloat16(y - __bfloat162float(hy)));
    hi = *(uint32_t*)&h;
    lo = *(uint32_t*)&l;
}
__device__ __forceinline__ void split2h(float x, float y, uint32_t& hi, uint32_t& lo) {
    __half hx = __float2half(x), hy = __float2half(y);
    __half2 h(hx, hy);
    __half2 l(__float2half(x - __half2float(hx)), __float2half(y - __half2float(hy)));
    hi = *(uint32_t*)&h;
    lo = *(uint32_t*)&l;
}

// ---------------- fp32 -> fp16 hi/lo split ------------------------------------
__global__ void cvt_split_h(const float* __restrict__ src,
                            __half* __restrict__ hi,
                            __half* __restrict__ lo, int n4)
{
    int i = blockIdx.x * blockDim.x + threadIdx.x;
    if (i >= n4) return;
    float4 v = ((const float4*)src)[i];
    uint32_t h0, l0, h1, l1;
    split2h(v.x, v.y, h0, l0);
    split2h(v.z, v.w, h1, l1);
    *(uint2*)(hi + (size_t)i * 4) = make_uint2(h0, h1);
    *(uint2*)(lo + (size_t)i * 4) = make_uint2(l0, l1);
}
// hi only (weights: low bits unused by 2-pass GEMM)
__global__ void cvt_h(const float* __restrict__ src, __half* __restrict__ hi, int n4)
{
    int i = blockIdx.x * blockDim.x + threadIdx.x;
    if (i >= n4) return;
    float4 v = ((const float4*)src)[i];
    __half2 a(__float2half(v.x), __float2half(v.y));
    __half2 b(__float2half(v.z), __float2half(v.w));
    *(uint2*)(hi + (size_t)i * 4) = make_uint2(*(uint32_t*)&a, *(uint32_t*)&b);
}

// ---------------- GEMM: 2-pass fp16 split, C[m][n]=sum_k A[m][k]*B[n][k] ------
// CTA 128x256x32, 8 warps (64x64 each). Stage: Ah 0, Al 10240, Bh 20480 -> 40960.
#define ROWB 80
#define GSTAGE 40960
#define GSM (2 * GSTAGE)

__global__ __launch_bounds__(256, 1) void gemm_hf(
    const __half* __restrict__ Ah, const __half* __restrict__ Al,
    const __half* __restrict__ Bh,
    float* __restrict__ C, int M, int N, int K)
{
    extern __shared__ __align__(128) char smem[];
    const uint32_t sb = smem_u32(smem);
    const int tid = threadIdx.x;
    const int lane = tid & 31, warp = tid >> 5;
    const int wm = warp >> 2, wn = warp & 3;
    const int bm = blockIdx.y * 128, bn = blockIdx.x * 256;
    const int NC = K / 32;

    const int ar = tid >> 2, ac = tid & 3;

    auto issue_stage = [&](int slot, int k0) {
        const uint32_t st = sb + slot * GSTAGE;
        {
            uint32_t d = st + ar * ROWB + ac * 16;
            const size_t s0 = (size_t)(bm + ar) * K + k0 + ac * 8;
            CP_ASYNC16(d,         Ah + s0);
            CP_ASYNC16(d + 10240, Al + s0);
            uint32_t d2 = st + (ar + 64) * ROWB + ac * 16;
            const size_t s2 = (size_t)(bm + ar + 64) * K + k0 + ac * 8;
            CP_ASYNC16(d2,         Ah + s2);
            CP_ASYNC16(d2 + 10240, Al + s2);
        }
#pragma unroll
        for (int i = 0; i < 4; i++) {
            int c = tid + i * 256;
            int br = c >> 2, bc = c & 3;
            uint32_t d = st + 20480 + br * ROWB + bc * 16;
            const size_t s0 = (size_t)(bn + br) * K + k0 + bc * 8;
            CP_ASYNC16(d, Bh + s0);
        }
    };

    issue_stage(0, 0);
    CP_COMMIT();

    float acc[32][4] = {};

    const uint32_t aoff = (uint32_t)((wm * 64 + (lane & 15)) * ROWB + (lane >> 4) * 16);
    const uint32_t boff = (uint32_t)(20480 + (wn * 64 + (lane & 7)) * ROWB +
                                     ((lane >> 3) & 1) * 16);

    for (int i = 0; i < NC; i++) {
        if (i > 0) __syncthreads();
        if (i + 1 < NC) { issue_stage((i + 1) & 1, (i + 1) * 32); CP_COMMIT(); CP_WAIT(1); }
        else           { CP_WAIT(0); }
        __syncthreads();

        const uint32_t st = sb + (i & 1) * GSTAGE;

#pragma unroll
        for (int kk = 0; kk < 2; kk++) {
            uint32_t ah[4][4], al[4][4], bh[8][2];
#pragma unroll
            for (int am = 0; am < 4; am++) {
                uint32_t ad = st + aoff + am * 16 * ROWB + kk * 32;
                ldm_x4(ah[am][0], ah[am][1], ah[am][2], ah[am][3], ad);
                ldm_x4(al[am][0], al[am][1], al[am][2], al[am][3], ad + 10240);
            }
#pragma unroll
            for (int nt = 0; nt < 8; nt++) {
                uint32_t bd = st + boff + nt * 8 * ROWB + kk * 32;
                ldm_x2(bh[nt][0], bh[nt][1], bd);
            }
            // 2 passes x 32 independent MMAs
#pragma unroll
            for (int am = 0; am < 4; am++)
#pragma unroll
                for (int nt = 0; nt < 8; nt++)
                    mma16816h(acc[am * 8 + nt], ah[am], bh[nt]);
#pragma unroll
            for (int am = 0; am < 4; am++)
#pragma unroll
                for (int nt = 0; nt < 8; nt++)
                    mma16816h(acc[am * 8 + nt], al[am], bh[nt]);
        }
    }

    const int er = bm + wm * 64 + (lane >> 2);
    const int ec = bn + wn * 64 + (lane & 3) * 2;
#pragma unroll
    for (int am = 0; am < 4; am++)
#pragma unroll
        for (int nt = 0; nt < 8; nt++) {
            float* d = acc[am * 8 + nt];
            int r = er + am * 16;
            int c = ec + nt * 8;
            *(float2*)(C + (size_t)r * N + c) = make_float2(d[0], d[1]);
            *(float2*)(C + (size_t)(r + 8) * N + c) = make_float2(d[2], d[3]);
        }
}

// ---------------- RoPE + split bf16 q/k/v + q0/k0 norms ----------------------
__global__ __launch_bounds__(256) void rope_split(const float* __restrict__ qkv,
                                                  const float* __restrict__ hyp)
{
    int bi = blockIdx.x * 8 + (threadIdx.x >> 5);
    int h = bi % H_;
    int t = (bi / H_) % T_;
    int b = bi / (H_ * T_);
    int j = threadIdx.x & 31;

    const float* src = qkv + (size_t)(b * T_ + t) * (3 * C_) + h * HD;
    float kc = hyp[h];

    float inv = powf(10000.0f, -(float)(2 * j) / 64.0f);
    float fr = (float)t * inv;
    float cs = cosf(fr);
    float sn = sinf(fr);

    size_t dst = ((size_t)(b * H_ + h) * T_ + t) * HD;

    float q1 = src[j], q2 = src[j + 32];
    float qo1 = q1 * cs + q2 * sn;
    float qo2 = -q1 * sn + q2 * cs;
    float k1 = src[C_ + j], k2 = src[C_ + j + 32];
    float ko1 = k1 * cs + k2 * sn;
    float ko2 = -k1 * sn + k2 * cs;
    float v1 = src[2 * C_ + j], v2 = src[2 * C_ + j + 32];

    __nv_bfloat16 hh;
    hh = __float2bfloat16(qo1); g_qh[dst + j] = hh;
    g_ql[dst + j] = __float2bfloat16(qo1 - __bfloat162float(hh));
    hh = __float2bfloat16(qo2); g_qh[dst + j + 32] = hh;
    g_ql[dst + j + 32] = __float2bfloat16(qo2 - __bfloat162float(hh));
    hh = __float2bfloat16(ko1); g_kh[dst + j] = hh;
    g_kl[dst + j] = __float2bfloat16(ko1 - __bfloat162float(hh));
    hh = __float2bfloat16(ko2); g_kh[dst + j + 32] = hh;
    g_kl[dst + j + 32] = __float2bfloat16(ko2 - __bfloat162float(hh));
    hh = __float2bfloat16(v1); g_vh[dst + j] = hh;
    g_vl[dst + j] = __float2bfloat16(v1 - __bfloat162float(hh));
    hh = __float2bfloat16(v2); g_vh[dst + j + 32] = hh;
    g_vl[dst + j + 32] = __float2bfloat16(v2 - __bfloat162float(hh));

    float sq = qo1 * qo1 + qo2 * qo2;
    float sk = ko1 * ko1 + ko2 * ko2;
#pragma unroll
    for (int off = 16; off; off >>= 1) {
        sq += __shfl_xor_sync(0xffffffffu, sq, off);
        sk += __shfl_xor_sync(0xffffffffu, sk, off);
    }
    if (j == 0) {
        size_t r = (size_t)(b * H_ + h) * T_ + t;
        g_q0[r] = sqrtf(kc + sq);
        g_k0[r] = sqrtf(kc + sk);
    }
}

// ---------------- per-score hyperbolic transform (4 MUFU) ---------------------
__device__ __forceinline__ float score_p(float s, float q0, float k0,
                                         float invk, float c1) {
    float inner = s - q0 * k0;
    float arg = fmaxf(-inner * invk, 1.000001f);
    float t = fmaf(arg, arg, -1.0f);
    float sq; asm("sqrt.approx.f32 %0, %1;" : "=f"(sq) : "f"(t));
    float y = arg + sq;
    float lg; asm("lg2.approx.f32 %0, %1;" : "=f"(lg) : "f"(y));
    float u = fmaf(c1, lg, 1e-6f);
    float w; asm("rcp.approx.f32 %0, %1;" : "=f"(w) : "f"(u));
    w = fminf(w, 60.0f);
    float p; asm("ex2.approx.f32 %0, %1;" : "=f"(p) : "f"(w * 1.44269504f));
    return p;
}

// ---------------- tensorized attention (bf16 3-pass, fp16 epilogue) -----------
#define AROWB 144
#define REG0 0
#define REG1 36864
#define SK0A 73728
#define ATT_SMEM 74240

__global__ __launch_bounds__(256, 1) void attn_mma(const float* __restrict__ hyp)
{
    extern __shared__ __align__(128) char smem[];
    const uint32_t sb = smem_u32(smem);
    const int tid = threadIdx.x;
    const int lane = tid & 31, warp = tid >> 5;
    const int qt = (int)gridDim.x - 1 - (int)blockIdx.x;
    const int h = blockIdx.y, b = blockIdx.z;
    const size_t bh = (size_t)b * H_ + h;
    const size_t qbase = (bh * T_ + (size_t)qt * 128) * HD;
    const size_t kvbase = bh * T_ * HD;
    const float* k0g = g_k0 + bh * T_;

    const float kc   = hyp[h];
    const float invk = 1.0f / kc;
    const float c1   = sqrtf(kc) * 0.69314718056f;

    const int ar0 = tid >> 3, ac0 = tid & 7;
    const int ar1 = (tid + 256) >> 3;

#pragma unroll
    for (int i = 0; i < 4; i++) {
        int ch = tid + i * 256;
        int row = ch >> 3, cc = ch & 7;
        uint32_t d = sb + REG0 + row * AROWB + cc * 16;
        CP_ASYNC16(d, g_qh + qbase + row * 64 + cc * 8);
        CP_ASYNC16(d + 18432, g_ql + qbase + row * 64 + cc * 8);
    }
    CP_COMMIT();

    auto issue_kv = [&](uint32_t reg, int st) {
        const uint32_t sk = sb + reg;
        const size_t tb = kvbase + (size_t)st * 64 * 64;
        uint32_t d0 = sk + ar0 * AROWB + ac0 * 16;
        const size_t s0 = tb + ar0 * 64 + ac0 * 8;
        CP_ASYNC16(d0,         g_kh + s0);
        CP_ASYNC16(d0 + 9216,  g_kl + s0);
        CP_ASYNC16(d0 + 18432, g_vh + s0);
        CP_ASYNC16(d0 + 27648, g_vl + s0);
        uint32_t d1 = sk + ar1 * AROWB + ac0 * 16;
        const size_t s1 = tb + ar1 * 64 + ac0 * 8;
        CP_ASYNC16(d1,         g_kh + s1);
        CP_ASYNC16(d1 + 9216,  g_kl + s1);
        CP_ASYNC16(d1 + 18432, g_vh + s1);
        CP_ASYNC16(d1 + 27648, g_vl + s1);
        if (tid < 16) CP_ASYNC16(sb + SK0A + (st & 1) * 256 + tid * 16,
                                 k0g + st * 64 + tid * 4);
    };

    const int ntile = 2 * qt + 2;
    issue_kv(REG1, 0);
    CP_COMMIT();

    CP_WAIT(1);
    __syncthreads();
    uint32_t qa_h[4][4], qa_l[4][4];
    const uint32_t qoff = (uint32_t)((warp * 16 + (lane & 15)) * AROWB + (lane >> 4) * 16);
#pragma unroll
    for (int g = 0; g < 4; g++) {
        ldm_x4(qa_h[g][0], qa_h[g][1], qa_h[g][2], qa_h[g][3], sb + REG0 + qoff + g * 32);
        ldm_x4(qa_l[g][0], qa_l[g][1], qa_l[g][2], qa_l[g][3], sb + REG0 + 18432 + qoff + g * 32);
    }

    const int r_in  = lane >> 2;
    const int cpair = (lane & 3) * 2;
    const int qr0 = qt * 128 + warp * 16 + r_in;
    const int qr1 = qr0 + 8;
    const float q00 = g_q0[bh * T_ + qr0];
    const float q01 = g_q0[bh * T_ + qr1];

    float O[8][4] = {};
    float ls0 = 0.0f, ls1 = 0.0f;

    const uint32_t kfb = (uint32_t)((lane & 7) * AROWB + ((lane >> 3) & 1) * 16);
    const uint32_t vfb = (uint32_t)((lane & 15) * AROWB);

    for (int st = 0; st < ntile; st++) {
        __syncthreads();
        if (st + 1 < ntile) {
            issue_kv((st & 1) ? REG1 : REG0, st + 1);
            CP_COMMIT();
        }
        if (st + 1 < ntile) { CP_WAIT(1); } else { CP_WAIT(0); }
        __syncthreads();

        const uint32_t reg = (st & 1) ? REG0 : REG1;
        const uint32_t sKh = sb + reg;
        const uint32_t sKl = sKh + 9216;
        const uint32_t sVh = sKh + 18432;
        const uint32_t sVl = sKh + 27648;
        const uint32_t k0off = SK0A + (st & 1) * 256;

        const bool maskT = (st >= 2 * qt);
        const int key_base = st * 64;

        float sacc[8][4] = {};
#pragma unroll
        for (int g = 0; g < 4; g++) {
            uint32_t kf[8][2];
#pragma unroll
            for (int nt = 0; nt < 8; nt++)
                ldm_x2(kf[nt][0], kf[nt][1], sKh + kfb + nt * 8 * AROWB + g * 32);
#pragma unroll
            for (int nt = 0; nt < 8; nt++) mma16816(sacc[nt], qa_h[g], kf[nt]);
#pragma unroll
            for (int nt = 0; nt < 8; nt++) mma16816(sacc[nt], qa_l[g], kf[nt]);
#pragma unroll
            for (int nt = 0; nt < 8; nt++)
                ldm_x2(kf[nt][0], kf[nt][1], sKl + kfb + nt * 8 * AROWB + g * 32);
#pragma unroll
            for (int nt = 0; nt < 8; nt++) mma16816(sacc[nt], qa_h[g], kf[nt]);
        }

        uint32_t pa_h[4][4], pa_l[4][4];
#pragma unroll
        for (int nt = 0; nt < 8; nt++) {
            float2 k0p = *(const float2*)(smem + k0off + (nt * 8 + cpair) * 4);
            const int keyc = key_base + nt * 8 + cpair;

            float p0 = score_p(sacc[nt][0], q00, k0p.x, invk, c1);
            float p1 = score_p(sacc[nt][1], q00, k0p.y, invk, c1);
            float p2 = score_p(sacc[nt][2], q01, k0p.x, invk, c1);
            float p3 = score_p(sacc[nt][3], q01, k0p.y, invk, c1);
            if (maskT) {
                if (keyc     > qr0) p0 = 0.0f;
                if (keyc + 1 > qr0) p1 = 0.0f;
                if (keyc     > qr1) p2 = 0.0f;
                if (keyc + 1 > qr1) p3 = 0.0f;
            }
            ls0 += p0 + p1;
            ls1 += p2 + p3;

            const int g = nt >> 1;
            const int rb = (nt & 1) * 2;
            split2(p0, p1, pa_h[g][rb + 0], pa_l[g][rb + 0]);
            split2(p2, p3, pa_h[g][rb + 1], pa_l[g][rb + 1]);
        }

#pragma unroll
        for (int g = 0; g < 4; g++) {
            uint32_t vf[8][2];
#pragma unroll
            for (int dt = 0; dt < 8; dt++)
                ldm_x2t(vf[dt][0], vf[dt][1], sVh + vfb + g * 16 * AROWB + dt * 16);
#pragma unroll
            for (int dt = 0; dt < 8; dt++) mma16816(O[dt], pa_h[g], vf[dt]);
#pragma unroll
            for (int dt = 0; dt < 8; dt++) mma16816(O[dt], pa_l[g], vf[dt]);
#pragma unroll
            for (int dt = 0; dt < 8; dt++)
                ldm_x2t(vf[dt][0], vf[dt][1], sVl + vfb + g * 16 * AROWB + dt * 16);
#pragma unroll
            for (int dt = 0; dt < 8; dt++) mma16816(O[dt], pa_h[g], vf[dt]);
        }
    }

    ls0 += __shfl_xor_sync(0xffffffffu, ls0, 1);
    ls0 += __shfl_xor_sync(0xffffffffu, ls0, 2);
    ls1 += __shfl_xor_sync(0xffffffffu, ls1, 1);
    ls1 += __shfl_xor_sync(0xffffffffu, ls1, 2);
    const float n0 = 1.0f / ls0;
    const float n1 = 1.0f / ls1;

    // epilogue: fp16 split (for 2-pass GEMM2)
    const size_t o0 = ((size_t)b * T_ + qr0) * C_ + h * 64;
    const size_t o1 = ((size_t)b * T_ + qr1) * C_ + h * 64;
#pragma unroll
    for (int dt = 0; dt < 8; dt++) {
        const int c = dt * 8 + cpair;
        uint32_t hh, ll;
        split2h(O[dt][0] * n0, O[dt][1] * n0, hh, ll);
        *(uint32_t*)(g_oh + o0 + c) = hh;
        *(uint32_t*)(g_ol + o0 + c) = ll;
        split2h(O[dt][2] * n1, O[dt][3] * n1, hh, ll);
        *(uint32_t*)(g_oh + o1 + c) = hh;
        *(uint32_t*)(g_ol + o1 + c) = ll;
    }
}

// ---------------- launch ------------------------------------------------------
extern "C" void kernel_launch(void* const* d_in, const int* in_sizes, int n_in,
                              void* d_out, int out_size)
{
    const float* x    = (const float*)d_in[0];
    const float* Wqkv = (const float*)d_in[1];
    const float* Wout = (const float*)d_in[2];
    const float* hyp  = (const float*)d_in[3];
    float* out = (float*)d_out;

    static float* p_qkv = nullptr;
    static __half *p_xh, *p_xl, *p_w1h, *p_w2h, *p_oh, *p_ol;
    if (!p_qkv) {
        cudaGetSymbolAddress((void**)&p_qkv, g_qkv);
        cudaGetSymbolAddress((void**)&p_xh, g_xh);
        cudaGetSymbolAddress((void**)&p_xl, g_xl);
        cudaGetSymbolAddress((void**)&p_w1h, g_w1h);
        cudaGetSymbolAddress((void**)&p_w2h, g_w2h);
        cudaGetSymbolAddress((void**)&p_oh, g_oh);
        cudaGetSymbolAddress((void**)&p_ol, g_ol);
        cudaFuncSetAttribute(gemm_hf,
                             cudaFuncAttributeMaxDynamicSharedMemorySize, GSM);
        cudaFuncSetAttribute(attn_mma,
                             cudaFuncAttributeMaxDynamicSharedMemorySize, ATT_SMEM);
    }

    // 0) conversions: x -> fp16 hi/lo; weights -> fp16 hi only
    cvt_split_h<<<(4096 * 1024 / 4 + 255) / 256, 256>>>(x, p_xh, p_xl, 4096 * 1024 / 4);
    cvt_h<<<(3072 * 1024 / 4 + 255) / 256, 256>>>(Wqkv, p_w1h, 3072 * 1024 / 4);
    cvt_h<<<(1024 * 1024 / 4 + 255) / 256, 256>>>(Wout, p_w2h, 1024 * 1024 / 4);

    // 1) qkv = x @ W_qkv^T  (2-pass fp16)
    gemm_hf<<<dim3(3072 / 256, 4096 / 128), 256, GSM>>>(
        p_xh, p_xl, p_w1h, p_qkv, 4096, 3072, 1024);

    // 2) RoPE + split + norms
    rope_split<<<B_ * T_ * H_ / 8, 256>>>(p_qkv, hyp);

    // 3) tensorized attention (bf16 3-pass)
    attn_mma<<<dim3(T_ / 128, H_, B_), 256, ATT_SMEM>>>(hyp);

    // 4) out = o @ W_out^T  (2-pass fp16)
    gemm_hf<<<dim3(1024 / 256, 4096 / 128), 256, GSM>>>(
        p_oh, p_ol, p_w2h, out, 4096, 1024, 1024);
}

// round 14
// speedup vs baseline: 1.3732x; 1.0996x over previous
#include <cuda_runtime.h>
#include <cuda_bf16.h>
#include <cuda_fp16.h>
#include <math.h>
#include <stdint.h>

#define B_ 4
#define T_ 1024
#define C_ 1024
#define H_ 16
#define HD 64

// ---------------- scratch (static device globals; no allocation) -------------
__device__ __align__(16) float g_qkv[(size_t)4096 * 3072];
__device__ float g_q0[(size_t)B_ * H_ * T_];
__device__ float g_k0[(size_t)B_ * H_ * T_];
// fp16 split operands for the projection GEMMs
__device__ __align__(16) __half g_xh[(size_t)4096 * 1024];
__device__ __align__(16) __half g_xl[(size_t)4096 * 1024];
__device__ __align__(16) __half g_w1h[(size_t)3072 * 1024];
__device__ __align__(16) __half g_w2h[(size_t)1024 * 1024];
__device__ __align__(16) __half g_oh[(size_t)4096 * 1024];
__device__ __align__(16) __half g_ol[(size_t)4096 * 1024];
// fp16 attention operands: q split hi/lo, k/v hi only
__device__ __align__(16) __half g_qh[(size_t)4096 * 1024];
__device__ __align__(16) __half g_ql[(size_t)4096 * 1024];
__device__ __align__(16) __half g_kh[(size_t)4096 * 1024];
__device__ __align__(16) __half g_vh[(size_t)4096 * 1024];

// ---------------- helpers ------------------------------------------------------
__device__ __forceinline__ uint32_t smem_u32(const void* p) {
    uint32_t a;
    asm("{ .reg .u64 t; cvta.to.shared.u64 t, %1; cvt.u32.u64 %0, t; }" : "=r"(a) : "l"(p));
    return a;
}
#define CP_ASYNC16(d, s)  asm volatile("cp.async.cg.shared.global [%0], [%1], 16;" :: "r"(d), "l"(s))
#define CP_COMMIT()       asm volatile("cp.async.commit_group;" ::: "memory")
#define CP_WAIT(n)        asm volatile("cp.async.wait_group %0;" :: "n"(n) : "memory")

__device__ __forceinline__ void ldm_x4(uint32_t& r0, uint32_t& r1, uint32_t& r2, uint32_t& r3,
                                       uint32_t addr) {
    asm volatile("ldmatrix.sync.aligned.m8n8.x4.shared.b16 {%0,%1,%2,%3}, [%4];"
                 : "=r"(r0), "=r"(r1), "=r"(r2), "=r"(r3) : "r"(addr));
}
__device__ __forceinline__ void ldm_x2(uint32_t& r0, uint32_t& r1, uint32_t addr) {
    asm volatile("ldmatrix.sync.aligned.m8n8.x2.shared.b16 {%0,%1}, [%2];"
                 : "=r"(r0), "=r"(r1) : "r"(addr));
}
__device__ __forceinline__ void ldm_x2t(uint32_t& r0, uint32_t& r1, uint32_t addr) {
    asm volatile("ldmatrix.sync.aligned.m8n8.x2.trans.shared.b16 {%0,%1}, [%2];"
                 : "=r"(r0), "=r"(r1) : "r"(addr));
}
// fp16 mma
__device__ __forceinline__ void mma16816h(float* d, const uint32_t* a, const uint32_t* b) {
    asm volatile("mma.sync.aligned.m16n8k16.row.col.f32.f16.f16.f32 "
                 "{%0,%1,%2,%3}, {%4,%5,%6,%7}, {%8,%9}, {%0,%1,%2,%3};"
                 : "+f"(d[0]), "+f"(d[1]), "+f"(d[2]), "+f"(d[3])
                 : "r"(a[0]), "r"(a[1]), "r"(a[2]), "r"(a[3]), "r"(b[0]), "r"(b[1]));
}
__device__ __forceinline__ void split2h(float x, float y, uint32_t& hi, uint32_t& lo) {
    __half hx = __float2half(x), hy = __float2half(y);
    __half2 h(hx, hy);
    __half2 l(__float2half(x - __half2float(hx)), __float2half(y - __half2float(hy)));
    hi = *(uint32_t*)&h;
    lo = *(uint32_t*)&l;
}

// ---------------- fp32 -> fp16 hi/lo split ------------------------------------
__global__ void cvt_split_h(const float* __restrict__ src,
                            __half* __restrict__ hi,
                            __half* __restrict__ lo, int n4)
{
    int i = blockIdx.x * blockDim.x + threadIdx.x;
    if (i >= n4) return;
    float4 v = ((const float4*)src)[i];
    uint32_t h0, l0, h1, l1;
    split2h(v.x, v.y, h0, l0);
    split2h(v.z, v.w, h1, l1);
    *(uint2*)(hi + (size_t)i * 4) = make_uint2(h0, h1);
    *(uint2*)(lo + (size_t)i * 4) = make_uint2(l0, l1);
}
__global__ void cvt_h(const float* __restrict__ src, __half* __restrict__ hi, int n4)
{
    int i = blockIdx.x * blockDim.x + threadIdx.x;
    if (i >= n4) return;
    float4 v = ((const float4*)src)[i];
    __half2 a(__float2half(v.x), __float2half(v.y));
    __half2 b(__float2half(v.z), __float2half(v.w));
    *(uint2*)(hi + (size_t)i * 4) = make_uint2(*(uint32_t*)&a, *(uint32_t*)&b);
}

// ---------------- GEMM: 2-pass fp16 split (unchanged from R13) ----------------
#define ROWB 80
#define GSTAGE 40960
#define GSM (2 * GSTAGE)

__global__ __launch_bounds__(256, 1) void gemm_hf(
    const __half* __restrict__ Ah, const __half* __restrict__ Al,
    const __half* __restrict__ Bh,
    float* __restrict__ C, int M, int N, int K)
{
    extern __shared__ __align__(128) char smem[];
    const uint32_t sb = smem_u32(smem);
    const int tid = threadIdx.x;
    const int lane = tid & 31, warp = tid >> 5;
    const int wm = warp >> 2, wn = warp & 3;
    const int bm = blockIdx.y * 128, bn = blockIdx.x * 256;
    const int NC = K / 32;

    const int ar = tid >> 2, ac = tid & 3;

    auto issue_stage = [&](int slot, int k0) {
        const uint32_t st = sb + slot * GSTAGE;
        {
            uint32_t d = st + ar * ROWB + ac * 16;
            const size_t s0 = (size_t)(bm + ar) * K + k0 + ac * 8;
            CP_ASYNC16(d,         Ah + s0);
            CP_ASYNC16(d + 10240, Al + s0);
            uint32_t d2 = st + (ar + 64) * ROWB + ac * 16;
            const size_t s2 = (size_t)(bm + ar + 64) * K + k0 + ac * 8;
            CP_ASYNC16(d2,         Ah + s2);
            CP_ASYNC16(d2 + 10240, Al + s2);
        }
#pragma unroll
        for (int i = 0; i < 4; i++) {
            int c = tid + i * 256;
            int br = c >> 2, bc = c & 3;
            uint32_t d = st + 20480 + br * ROWB + bc * 16;
            const size_t s0 = (size_t)(bn + br) * K + k0 + bc * 8;
            CP_ASYNC16(d, Bh + s0);
        }
    };

    issue_stage(0, 0);
    CP_COMMIT();

    float acc[32][4] = {};

    const uint32_t aoff = (uint32_t)((wm * 64 + (lane & 15)) * ROWB + (lane >> 4) * 16);
    const uint32_t boff = (uint32_t)(20480 + (wn * 64 + (lane & 7)) * ROWB +
                                     ((lane >> 3) & 1) * 16);

    for (int i = 0; i < NC; i++) {
        if (i > 0) __syncthreads();
        if (i + 1 < NC) { issue_stage((i + 1) & 1, (i + 1) * 32); CP_COMMIT(); CP_WAIT(1); }
        else           { CP_WAIT(0); }
        __syncthreads();

        const uint32_t st = sb + (i & 1) * GSTAGE;

#pragma unroll
        for (int kk = 0; kk < 2; kk++) {
            uint32_t ah[4][4], al[4][4], bh[8][2];
#pragma unroll
            for (int am = 0; am < 4; am++) {
                uint32_t ad = st + aoff + am * 16 * ROWB + kk * 32;
                ldm_x4(ah[am][0], ah[am][1], ah[am][2], ah[am][3], ad);
                ldm_x4(al[am][0], al[am][1], al[am][2], al[am][3], ad + 10240);
            }
#pragma unroll
            for (int nt = 0; nt < 8; nt++) {
                uint32_t bd = st + boff + nt * 8 * ROWB + kk * 32;
                ldm_x2(bh[nt][0], bh[nt][1], bd);
            }
#pragma unroll
            for (int am = 0; am < 4; am++)
#pragma unroll
                for (int nt = 0; nt < 8; nt++)
                    mma16816h(acc[am * 8 + nt], ah[am], bh[nt]);
#pragma unroll
            for (int am = 0; am < 4; am++)
#pragma unroll
                for (int nt = 0; nt < 8; nt++)
                    mma16816h(acc[am * 8 + nt], al[am], bh[nt]);
        }
    }

    const int er = bm + wm * 64 + (lane >> 2);
    const int ec = bn + wn * 64 + (lane & 3) * 2;
#pragma unroll
    for (int am = 0; am < 4; am++)
#pragma unroll
        for (int nt = 0; nt < 8; nt++) {
            float* d = acc[am * 8 + nt];
            int r = er + am * 16;
            int c = ec + nt * 8;
            *(float2*)(C + (size_t)r * N + c) = make_float2(d[0], d[1]);
            *(float2*)(C + (size_t)(r + 8) * N + c) = make_float2(d[2], d[3]);
        }
}

// ---------------- RoPE + fp16 q(hi/lo), k/v(hi) + q0/k0 norms -----------------
__global__ __launch_bounds__(256) void rope_split(const float* __restrict__ qkv,
                                                  const float* __restrict__ hyp)
{
    int bi = blockIdx.x * 8 + (threadIdx.x >> 5);
    int h = bi % H_;
    int t = (bi / H_) % T_;
    int b = bi / (H_ * T_);
    int j = threadIdx.x & 31;

    const float* src = qkv + (size_t)(b * T_ + t) * (3 * C_) + h * HD;
    float kc = hyp[h];

    float inv = powf(10000.0f, -(float)(2 * j) / 64.0f);
    float fr = (float)t * inv;
    float cs = cosf(fr);
    float sn = sinf(fr);

    size_t dst = ((size_t)(b * H_ + h) * T_ + t) * HD;

    float q1 = src[j], q2 = src[j + 32];
    float qo1 = q1 * cs + q2 * sn;
    float qo2 = -q1 * sn + q2 * cs;
    float k1 = src[C_ + j], k2 = src[C_ + j + 32];
    float ko1 = k1 * cs + k2 * sn;
    float ko2 = -k1 * sn + k2 * cs;
    float v1 = src[2 * C_ + j], v2 = src[2 * C_ + j + 32];

    __half hh;
    hh = __float2half(qo1); g_qh[dst + j] = hh;
    g_ql[dst + j] = __float2half(qo1 - __half2float(hh));
    hh = __float2half(qo2); g_qh[dst + j + 32] = hh;
    g_ql[dst + j + 32] = __float2half(qo2 - __half2float(hh));
    g_kh[dst + j]      = __float2half(ko1);
    g_kh[dst + j + 32] = __float2half(ko2);
    g_vh[dst + j]      = __float2half(v1);
    g_vh[dst + j + 32] = __float2half(v2);

    float sq = qo1 * qo1 + qo2 * qo2;
    float sk = ko1 * ko1 + ko2 * ko2;
#pragma unroll
    for (int off = 16; off; off >>= 1) {
        sq += __shfl_xor_sync(0xffffffffu, sq, off);
        sk += __shfl_xor_sync(0xffffffffu, sk, off);
    }
    if (j == 0) {
        size_t r = (size_t)(b * H_ + h) * T_ + t;
        g_q0[r] = sqrtf(kc + sq);
        g_k0[r] = sqrtf(kc + sk);
    }
}

// ---------------- per-score hyperbolic transform (4 MUFU) ---------------------
__device__ __forceinline__ float score_p(float s, float q0, float k0,
                                         float invk, float c1) {
    float inner = s - q0 * k0;
    float arg = fmaxf(-inner * invk, 1.000001f);
    float t = fmaf(arg, arg, -1.0f);
    float sq; asm("sqrt.approx.f32 %0, %1;" : "=f"(sq) : "f"(t));
    float y = arg + sq;
    float lg; asm("lg2.approx.f32 %0, %1;" : "=f"(lg) : "f"(y));
    float u = fmaf(c1, lg, 1e-6f);
    float w; asm("rcp.approx.f32 %0, %1;" : "=f"(w) : "f"(u));
    w = fminf(w, 60.0f);
    float p; asm("ex2.approx.f32 %0, %1;" : "=f"(p) : "f"(w * 1.44269504f));
    return p;
}

// ---------------- tensorized attention: fp16 2-pass QK and PV -----------------
// smem: Qh 0..18432, Ql 18432..36864; KV stage s at 36864 + s*18432
//       (kh +0, vh +9216); k0 2x256 at 73728.
#define AROWB 144
#define SQH 0
#define SQL 18432
#define SKV 36864
#define KVSTG 18432
#define SK0A 73728
#define ATT_SMEM 74240

__global__ __launch_bounds__(256, 1) void attn_mma(const float* __restrict__ hyp)
{
    extern __shared__ __align__(128) char smem[];
    const uint32_t sb = smem_u32(smem);
    const int tid = threadIdx.x;
    const int lane = tid & 31, warp = tid >> 5;
    const int qt = (int)gridDim.x - 1 - (int)blockIdx.x;
    const int h = blockIdx.y, b = blockIdx.z;
    const size_t bh = (size_t)b * H_ + h;
    const size_t qbase = (bh * T_ + (size_t)qt * 128) * HD;
    const size_t kvbase = bh * T_ * HD;
    const float* k0g = g_k0 + bh * T_;

    const float kc   = hyp[h];
    const float invk = 1.0f / kc;
    const float c1   = sqrtf(kc) * 0.69314718056f;

    const int ar0 = tid >> 3, ac0 = tid & 7;          // rows 0..31
    const int ar1 = (tid + 256) >> 3;                 // rows 32..63

    // ---- Q loads (128 rows x 8 chunks; hi + lo)
#pragma unroll
    for (int i = 0; i < 4; i++) {
        int ch = tid + i * 256;
        int row = ch >> 3, cc = ch & 7;
        uint32_t d = sb + SQH + row * AROWB + cc * 16;
        CP_ASYNC16(d, g_qh + qbase + row * 64 + cc * 8);
        CP_ASYNC16(d + (SQL - SQH), g_ql + qbase + row * 64 + cc * 8);
    }
    CP_COMMIT();

    auto issue_kv = [&](int slot, int st) {
        const uint32_t sk = sb + SKV + slot * KVSTG;
        const size_t tb = kvbase + (size_t)st * 64 * 64;
        uint32_t d0 = sk + ar0 * AROWB + ac0 * 16;
        const size_t s0 = tb + ar0 * 64 + ac0 * 8;
        CP_ASYNC16(d0,        g_kh + s0);
        CP_ASYNC16(d0 + 9216, g_vh + s0);
        uint32_t d1 = sk + ar1 * AROWB + ac0 * 16;
        const size_t s1 = tb + ar1 * 64 + ac0 * 8;
        CP_ASYNC16(d1,        g_kh + s1);
        CP_ASYNC16(d1 + 9216, g_vh + s1);
        if (tid < 16) CP_ASYNC16(sb + SK0A + slot * 256 + tid * 16,
                                 k0g + st * 64 + tid * 4);
    };

    const int ntile = 2 * qt + 2;
    issue_kv(0, 0);
    CP_COMMIT();

    // ---- wait for Q, extract fragments
    CP_WAIT(1);
    __syncthreads();
    uint32_t qa_h[4][4], qa_l[4][4];
    const uint32_t qoff = (uint32_t)((warp * 16 + (lane & 15)) * AROWB + (lane >> 4) * 16);
#pragma unroll
    for (int g = 0; g < 4; g++) {
        ldm_x4(qa_h[g][0], qa_h[g][1], qa_h[g][2], qa_h[g][3], sb + SQH + qoff + g * 32);
        ldm_x4(qa_l[g][0], qa_l[g][1], qa_l[g][2], qa_l[g][3], sb + SQL + qoff + g * 32);
    }

    const int r_in  = lane >> 2;
    const int cpair = (lane & 3) * 2;
    const int qr0 = qt * 128 + warp * 16 + r_in;
    const int qr1 = qr0 + 8;
    const float q00 = g_q0[bh * T_ + qr0];
    const float q01 = g_q0[bh * T_ + qr1];

    float O[8][4] = {};
    float ls0 = 0.0f, ls1 = 0.0f;

    const uint32_t kfb = (uint32_t)((lane & 7) * AROWB + ((lane >> 3) & 1) * 16);
    const uint32_t vfb = (uint32_t)((lane & 15) * AROWB);

    for (int st = 0; st < ntile; st++) {
        __syncthreads();
        if (st + 1 < ntile) {
            issue_kv((st + 1) & 1, st + 1);
            CP_COMMIT();
        }
        if (st + 1 < ntile) { CP_WAIT(1); } else { CP_WAIT(0); }
        __syncthreads();

        const uint32_t sKh = sb + SKV + (st & 1) * KVSTG;
        const uint32_t sVh = sKh + 9216;
        const uint32_t k0off = SK0A + (st & 1) * 256;

        const bool maskT = (st >= 2 * qt);
        const int key_base = st * 64;

        // ---- S = Q K^T (2 passes: Qh, Ql vs Kh)
        float sacc[8][4] = {};
#pragma unroll
        for (int g = 0; g < 4; g++) {
            uint32_t kf[8][2];
#pragma unroll
            for (int nt = 0; nt < 8; nt++)
                ldm_x2(kf[nt][0], kf[nt][1], sKh + kfb + nt * 8 * AROWB + g * 32);
#pragma unroll
            for (int nt = 0; nt < 8; nt++) mma16816h(sacc[nt], qa_h[g], kf[nt]);
#pragma unroll
            for (int nt = 0; nt < 8; nt++) mma16816h(sacc[nt], qa_l[g], kf[nt]);
        }

        // ---- transform + pack P (fp16 split)
        uint32_t pa_h[4][4], pa_l[4][4];
#pragma unroll
        for (int nt = 0; nt < 8; nt++) {
            float2 k0p = *(const float2*)(smem + k0off + (nt * 8 + cpair) * 4);
            const int keyc = key_base + nt * 8 + cpair;

            float p0 = score_p(sacc[nt][0], q00, k0p.x, invk, c1);
            float p1 = score_p(sacc[nt][1], q00, k0p.y, invk, c1);
            float p2 = score_p(sacc[nt][2], q01, k0p.x, invk, c1);
            float p3 = score_p(sacc[nt][3], q01, k0p.y, invk, c1);
            if (maskT) {
                if (keyc     > qr0) p0 = 0.0f;
                if (keyc + 1 > qr0) p1 = 0.0f;
                if (keyc     > qr1) p2 = 0.0f;
                if (keyc + 1 > qr1) p3 = 0.0f;
            }
            ls0 += p0 + p1;
            ls1 += p2 + p3;

            const int g = nt >> 1;
            const int rb = (nt & 1) * 2;
            split2h(p0, p1, pa_h[g][rb + 0], pa_l[g][rb + 0]);
            split2h(p2, p3, pa_h[g][rb + 1], pa_l[g][rb + 1]);
        }

        // ---- O += P V (2 passes: Ph, Pl vs Vh)
#pragma unroll
        for (int g = 0; g < 4; g++) {
            uint32_t vf[8][2];
#pragma unroll
            for (int dt = 0; dt < 8; dt++)
                ldm_x2t(vf[dt][0], vf[dt][1], sVh + vfb + g * 16 * AROWB + dt * 16);
#pragma unroll
            for (int dt = 0; dt < 8; dt++) mma16816h(O[dt], pa_h[g], vf[dt]);
#pragma unroll
            for (int dt = 0; dt < 8; dt++) mma16816h(O[dt], pa_l[g], vf[dt]);
        }
    }

    ls0 += __shfl_xor_sync(0xffffffffu, ls0, 1);
    ls0 += __shfl_xor_sync(0xffffffffu, ls0, 2);
    ls1 += __shfl_xor_sync(0xffffffffu, ls1, 1);
    ls1 += __shfl_xor_sync(0xffffffffu, ls1, 2);
    const float n0 = 1.0f / ls0;
    const float n1 = 1.0f / ls1;

    // epilogue: fp16 split for GEMM2
    const size_t o0 = ((size_t)b * T_ + qr0) * C_ + h * 64;
    const size_t o1 = ((size_t)b * T_ + qr1) * C_ + h * 64;
#pragma unroll
    for (int dt = 0; dt < 8; dt++) {
        const int c = dt * 8 + cpair;
        uint32_t hh, ll;
        split2h(O[dt][0] * n0, O[dt][1] * n0, hh, ll);
        *(uint32_t*)(g_oh + o0 + c) = hh;
        *(uint32_t*)(g_ol + o0 + c) = ll;
        split2h(O[dt][2] * n1, O[dt][3] * n1, hh, ll);
        *(uint32_t*)(g_oh + o1 + c) = hh;
        *(uint32_t*)(g_ol + o1 + c) = ll;
    }
}

// ---------------- launch ------------------------------------------------------
extern "C" void kernel_launch(void* const* d_in, const int* in_sizes, int n_in,
                              void* d_out, int out_size)
{
    const float* x    = (const float*)d_in[0];
    const float* Wqkv = (const float*)d_in[1];
    const float* Wout = (const float*)d_in[2];
    const float* hyp  = (const float*)d_in[3];
    float* out = (float*)d_out;

    static float* p_qkv = nullptr;
    static __half *p_xh, *p_xl, *p_w1h, *p_w2h, *p_oh, *p_ol;
    if (!p_qkv) {
        cudaGetSymbolAddress((void**)&p_qkv, g_qkv);
        cudaGetSymbolAddress((void**)&p_xh, g_xh);
        cudaGetSymbolAddress((void**)&p_xl, g_xl);
        cudaGetSymbolAddress((void**)&p_w1h, g_w1h);
        cudaGetSymbolAddress((void**)&p_w2h, g_w2h);
        cudaGetSymbolAddress((void**)&p_oh, g_oh);
        cudaGetSymbolAddress((void**)&p_ol, g_ol);
        cudaFuncSetAttribute(gemm_hf,
                             cudaFuncAttributeMaxDynamicSharedMemorySize, GSM);
        cudaFuncSetAttribute(attn_mma,
                             cudaFuncAttributeMaxDynamicSharedMemorySize, ATT_SMEM);
    }

    // 0) conversions
    cvt_split_h<<<(4096 * 1024 / 4 + 255) / 256, 256>>>(x, p_xh, p_xl, 4096 * 1024 / 4);
    cvt_h<<<(3072 * 1024 / 4 + 255) / 256, 256>>>(Wqkv, p_w1h, 3072 * 1024 / 4);
    cvt_h<<<(1024 * 1024 / 4 + 255) / 256, 256>>>(Wout, p_w2h, 1024 * 1024 / 4);

    // 1) qkv = x @ W_qkv^T  (2-pass fp16)
    gemm_hf<<<dim3(3072 / 256, 4096 / 128), 256, GSM>>>(
        p_xh, p_xl, p_w1h, p_qkv, 4096, 3072, 1024);

    // 2) RoPE + fp16 conversion + norms
    rope_split<<<B_ * T_ * H_ / 8, 256>>>(p_qkv, hyp);

    // 3) tensorized attention (fp16 2-pass)
    attn_mma<<<dim3(T_ / 128, H_, B_), 256, ATT_SMEM>>>(hyp);

    // 4) out = o @ W_out^T  (2-pass fp16)
    gemm_hf<<<dim3(1024 / 256, 4096 / 128), 256, GSM>>>(
        p_oh, p_ol, p_w2h, out, 4096, 1024, 1024);
}

// round 15
// speedup vs baseline: 1.9035x; 1.3862x over previous
#include <cuda_runtime.h>
#include <cuda_fp16.h>
#include <math.h>
#include <stdint.h>

#define B_ 4
#define T_ 1024
#define C_ 1024
#define H_ 16
#define HD 64

// ---------------- scratch (static device globals; no allocation) -------------
__device__ __align__(16) float g_qkv[(size_t)4096 * 3072];
__device__ float g_q0[(size_t)B_ * H_ * T_];
__device__ float g_k0[(size_t)B_ * H_ * T_];
__device__ __align__(16) __half g_xh[(size_t)4096 * 1024];
__device__ __align__(16) __half g_w1h[(size_t)3072 * 1024];
__device__ __align__(16) __half g_w2h[(size_t)1024 * 1024];
__device__ __align__(16) __half g_oh[(size_t)4096 * 1024];
__device__ __align__(16) __half g_qh[(size_t)4096 * 1024];
__device__ __align__(16) __half g_kh[(size_t)4096 * 1024];
__device__ __align__(16) __half g_vh[(size_t)4096 * 1024];

// ---------------- helpers ------------------------------------------------------
__device__ __forceinline__ uint32_t smem_u32(const void* p) {
    uint32_t a;
    asm("{ .reg .u64 t; cvta.to.shared.u64 t, %1; cvt.u32.u64 %0, t; }" : "=r"(a) : "l"(p));
    return a;
}
#define CP_ASYNC16(d, s)  asm volatile("cp.async.cg.shared.global [%0], [%1], 16;" :: "r"(d), "l"(s))
#define CP_COMMIT()       asm volatile("cp.async.commit_group;" ::: "memory")
#define CP_WAIT(n)        asm volatile("cp.async.wait_group %0;" :: "n"(n) : "memory")

__device__ __forceinline__ void ldm_x4(uint32_t& r0, uint32_t& r1, uint32_t& r2, uint32_t& r3,
                                       uint32_t addr) {
    asm volatile("ldmatrix.sync.aligned.m8n8.x4.shared.b16 {%0,%1,%2,%3}, [%4];"
                 : "=r"(r0), "=r"(r1), "=r"(r2), "=r"(r3) : "r"(addr));
}
__device__ __forceinline__ void ldm_x2(uint32_t& r0, uint32_t& r1, uint32_t addr) {
    asm volatile("ldmatrix.sync.aligned.m8n8.x2.shared.b16 {%0,%1}, [%2];"
                 : "=r"(r0), "=r"(r1) : "r"(addr));
}
__device__ __forceinline__ void ldm_x2t(uint32_t& r0, uint32_t& r1, uint32_t addr) {
    asm volatile("ldmatrix.sync.aligned.m8n8.x2.trans.shared.b16 {%0,%1}, [%2];"
                 : "=r"(r0), "=r"(r1) : "r"(addr));
}
__device__ __forceinline__ void mma16816h(float* d, const uint32_t* a, const uint32_t* b) {
    asm volatile("mma.sync.aligned.m16n8k16.row.col.f32.f16.f16.f32 "
                 "{%0,%1,%2,%3}, {%4,%5,%6,%7}, {%8,%9}, {%0,%1,%2,%3};"
                 : "+f"(d[0]), "+f"(d[1]), "+f"(d[2]), "+f"(d[3])
                 : "r"(a[0]), "r"(a[1]), "r"(a[2]), "r"(a[3]), "r"(b[0]), "r"(b[1]));
}
__device__ __forceinline__ uint32_t pack_h2(float x, float y) {
    __half2 h(__float2half(x), __float2half(y));
    return *(uint32_t*)&h;
}

// ---------------- fp32 -> fp16 --------------------------------------------------
__global__ void cvt_h(const float* __restrict__ src, __half* __restrict__ hi, int n4)
{
    int i = blockIdx.x * blockDim.x + threadIdx.x;
    if (i >= n4) return;
    float4 v = ((const float4*)src)[i];
    *(uint2*)(hi + (size_t)i * 4) = make_uint2(pack_h2(v.x, v.y), pack_h2(v.z, v.w));
}

// ---------------- GEMM: single-pass fp16, C[m][n]=sum_k A[m][k]*B[n][k] -------
// CTA 128x256x32, 8 warps (64x64). Stage: A 0 (10240), B 10240 (20480) = 30720.
#define ROWB 80
#define GSTAGE 30720
#define GSM (2 * GSTAGE)

__global__ __launch_bounds__(256, 1) void gemm_hf(
    const __half* __restrict__ Ah, const __half* __restrict__ Bh,
    float* __restrict__ C, int M, int N, int K)
{
    extern __shared__ __align__(128) char smem[];
    const uint32_t sb = smem_u32(smem);
    const int tid = threadIdx.x;
    const int lane = tid & 31, warp = tid >> 5;
    const int wm = warp >> 2, wn = warp & 3;
    const int bm = blockIdx.y * 128, bn = blockIdx.x * 256;
    const int NC = K / 32;

    const int ar = tid >> 2, ac = tid & 3;

    auto issue_stage = [&](int slot, int k0) {
        const uint32_t st = sb + slot * GSTAGE;
        {
            uint32_t d = st + ar * ROWB + ac * 16;
            const size_t s0 = (size_t)(bm + ar) * K + k0 + ac * 8;
            CP_ASYNC16(d, Ah + s0);
            uint32_t d2 = st + (ar + 64) * ROWB + ac * 16;
            const size_t s2 = (size_t)(bm + ar + 64) * K + k0 + ac * 8;
            CP_ASYNC16(d2, Ah + s2);
        }
#pragma unroll
        for (int i = 0; i < 4; i++) {
            int c = tid + i * 256;
            int br = c >> 2, bc = c & 3;
            uint32_t d = st + 10240 + br * ROWB + bc * 16;
            const size_t s0 = (size_t)(bn + br) * K + k0 + bc * 8;
            CP_ASYNC16(d, Bh + s0);
        }
    };

    issue_stage(0, 0);
    CP_COMMIT();

    float acc[32][4] = {};

    const uint32_t aoff = (uint32_t)((wm * 64 + (lane & 15)) * ROWB + (lane >> 4) * 16);
    const uint32_t boff = (uint32_t)(10240 + (wn * 64 + (lane & 7)) * ROWB +
                                     ((lane >> 3) & 1) * 16);

    for (int i = 0; i < NC; i++) {
        if (i > 0) __syncthreads();
        if (i + 1 < NC) { issue_stage((i + 1) & 1, (i + 1) * 32); CP_COMMIT(); CP_WAIT(1); }
        else           { CP_WAIT(0); }
        __syncthreads();

        const uint32_t st = sb + (i & 1) * GSTAGE;

#pragma unroll
        for (int kk = 0; kk < 2; kk++) {
            uint32_t ah[4][4], bh[8][2];
#pragma unroll
            for (int am = 0; am < 4; am++) {
                uint32_t ad = st + aoff + am * 16 * ROWB + kk * 32;
                ldm_x4(ah[am][0], ah[am][1], ah[am][2], ah[am][3], ad);
            }
#pragma unroll
            for (int nt = 0; nt < 8; nt++) {
                uint32_t bd = st + boff + nt * 8 * ROWB + kk * 32;
                ldm_x2(bh[nt][0], bh[nt][1], bd);
            }
#pragma unroll
            for (int am = 0; am < 4; am++)
#pragma unroll
                for (int nt = 0; nt < 8; nt++)
                    mma16816h(acc[am * 8 + nt], ah[am], bh[nt]);
        }
    }

    const int er = bm + wm * 64 + (lane >> 2);
    const int ec = bn + wn * 64 + (lane & 3) * 2;
#pragma unroll
    for (int am = 0; am < 4; am++)
#pragma unroll
        for (int nt = 0; nt < 8; nt++) {
            float* d = acc[am * 8 + nt];
            int r = er + am * 16;
            int c = ec + nt * 8;
            *(float2*)(C + (size_t)r * N + c) = make_float2(d[0], d[1]);
            *(float2*)(C + (size_t)(r + 8) * N + c) = make_float2(d[2], d[3]);
        }
}

// ---------------- RoPE + fp16 q/k/v + q0/k0 norms -----------------------------
__global__ __launch_bounds__(256) void rope_split(const float* __restrict__ qkv,
                                                  const float* __restrict__ hyp)
{
    int bi = blockIdx.x * 8 + (threadIdx.x >> 5);
    int h = bi % H_;
    int t = (bi / H_) % T_;
    int b = bi / (H_ * T_);
    int j = threadIdx.x & 31;

    const float* src = qkv + (size_t)(b * T_ + t) * (3 * C_) + h * HD;
    float kc = hyp[h];

    float inv = powf(10000.0f, -(float)(2 * j) / 64.0f);
    float fr = (float)t * inv;
    float cs = cosf(fr);
    float sn = sinf(fr);

    size_t dst = ((size_t)(b * H_ + h) * T_ + t) * HD;

    float q1 = src[j], q2 = src[j + 32];
    float qo1 = q1 * cs + q2 * sn;
    float qo2 = -q1 * sn + q2 * cs;
    float k1 = src[C_ + j], k2 = src[C_ + j + 32];
    float ko1 = k1 * cs + k2 * sn;
    float ko2 = -k1 * sn + k2 * cs;
    float v1 = src[2 * C_ + j], v2 = src[2 * C_ + j + 32];

    g_qh[dst + j]      = __float2half(qo1);
    g_qh[dst + j + 32] = __float2half(qo2);
    g_kh[dst + j]      = __float2half(ko1);
    g_kh[dst + j + 32] = __float2half(ko2);
    g_vh[dst + j]      = __float2half(v1);
    g_vh[dst + j + 32] = __float2half(v2);

    float sq = qo1 * qo1 + qo2 * qo2;
    float sk = ko1 * ko1 + ko2 * ko2;
#pragma unroll
    for (int off = 16; off; off >>= 1) {
        sq += __shfl_xor_sync(0xffffffffu, sq, off);
        sk += __shfl_xor_sync(0xffffffffu, sk, off);
    }
    if (j == 0) {
        size_t r = (size_t)(b * H_ + h) * T_ + t;
        g_q0[r] = sqrtf(kc + sq);
        g_k0[r] = sqrtf(kc + sk);
    }
}

// ---------------- per-score hyperbolic transform (4 MUFU) ---------------------
__device__ __forceinline__ float score_p(float s, float q0, float k0,
                                         float invk, float c1) {
    float inner = s - q0 * k0;
    float arg = fmaxf(-inner * invk, 1.000001f);
    float t = fmaf(arg, arg, -1.0f);
    float sq; asm("sqrt.approx.f32 %0, %1;" : "=f"(sq) : "f"(t));
    float y = arg + sq;
    float lg; asm("lg2.approx.f32 %0, %1;" : "=f"(lg) : "f"(y));
    float u = fmaf(c1, lg, 1e-6f);
    float w; asm("rcp.approx.f32 %0, %1;" : "=f"(w) : "f"(u));
    w = fminf(w, 60.0f);
    float p; asm("ex2.approx.f32 %0, %1;" : "=f"(p) : "f"(w * 1.44269504f));
    return p;
}

// ---------------- tensorized attention: single-pass fp16 QK and PV ------------
// smem: Qh 0..18432; KV stage s at 18432 + s*18432 (kh +0, vh +9216);
//       k0 2x256 at 55296. Total 55808.
#define AROWB 144
#define SQH 0
#define SKV 18432
#define KVSTG 18432
#define SK0A 55296
#define ATT_SMEM 55808

__global__ __launch_bounds__(256, 1) void attn_mma(const float* __restrict__ hyp)
{
    extern __shared__ __align__(128) char smem[];
    const uint32_t sb = smem_u32(smem);
    const int tid = threadIdx.x;
    const int lane = tid & 31, warp = tid >> 5;
    const int qt = (int)gridDim.x - 1 - (int)blockIdx.x;
    const int h = blockIdx.y, b = blockIdx.z;
    const size_t bh = (size_t)b * H_ + h;
    const size_t qbase = (bh * T_ + (size_t)qt * 128) * HD;
    const size_t kvbase = bh * T_ * HD;
    const float* k0g = g_k0 + bh * T_;

    const float kc   = hyp[h];
    const float invk = 1.0f / kc;
    const float c1   = sqrtf(kc) * 0.69314718056f;

    const int ar0 = tid >> 3, ac0 = tid & 7;          // rows 0..31
    const int ar1 = (tid + 256) >> 3;                 // rows 32..63

    // ---- Q loads (128 rows x 8 chunks, hi only)
#pragma unroll
    for (int i = 0; i < 4; i++) {
        int ch = tid + i * 256;
        int row = ch >> 3, cc = ch & 7;
        CP_ASYNC16(sb + SQH + row * AROWB + cc * 16, g_qh + qbase + row * 64 + cc * 8);
    }
    CP_COMMIT();

    auto issue_kv = [&](int slot, int st) {
        const uint32_t sk = sb + SKV + slot * KVSTG;
        const size_t tb = kvbase + (size_t)st * 64 * 64;
        uint32_t d0 = sk + ar0 * AROWB + ac0 * 16;
        const size_t s0 = tb + ar0 * 64 + ac0 * 8;
        CP_ASYNC16(d0,        g_kh + s0);
        CP_ASYNC16(d0 + 9216, g_vh + s0);
        uint32_t d1 = sk + ar1 * AROWB + ac0 * 16;
        const size_t s1 = tb + ar1 * 64 + ac0 * 8;
        CP_ASYNC16(d1,        g_kh + s1);
        CP_ASYNC16(d1 + 9216, g_vh + s1);
        if (tid < 16) CP_ASYNC16(sb + SK0A + slot * 256 + tid * 16,
                                 k0g + st * 64 + tid * 4);
    };

    const int ntile = 2 * qt + 2;
    issue_kv(0, 0);
    CP_COMMIT();

    // ---- wait for Q, extract fragments
    CP_WAIT(1);
    __syncthreads();
    uint32_t qa[4][4];
    const uint32_t qoff = (uint32_t)((warp * 16 + (lane & 15)) * AROWB + (lane >> 4) * 16);
#pragma unroll
    for (int g = 0; g < 4; g++)
        ldm_x4(qa[g][0], qa[g][1], qa[g][2], qa[g][3], sb + SQH + qoff + g * 32);

    const int r_in  = lane >> 2;
    const int cpair = (lane & 3) * 2;
    const int qr0 = qt * 128 + warp * 16 + r_in;
    const int qr1 = qr0 + 8;
    const float q00 = g_q0[bh * T_ + qr0];
    const float q01 = g_q0[bh * T_ + qr1];

    float O[8][4] = {};
    float ls0 = 0.0f, ls1 = 0.0f;

    const uint32_t kfb = (uint32_t)((lane & 7) * AROWB + ((lane >> 3) & 1) * 16);
    const uint32_t vfb = (uint32_t)((lane & 15) * AROWB);

    for (int st = 0; st < ntile; st++) {
        __syncthreads();
        if (st + 1 < ntile) {
            issue_kv((st + 1) & 1, st + 1);
            CP_COMMIT();
        }
        if (st + 1 < ntile) { CP_WAIT(1); } else { CP_WAIT(0); }
        __syncthreads();

        const uint32_t sKh = sb + SKV + (st & 1) * KVSTG;
        const uint32_t sVh = sKh + 9216;
        const uint32_t k0off = SK0A + (st & 1) * 256;

        const bool maskT = (st >= 2 * qt);
        const int key_base = st * 64;

        // ---- S = Q K^T (single pass)
        float sacc[8][4] = {};
#pragma unroll
        for (int g = 0; g < 4; g++) {
            uint32_t kf[8][2];
#pragma unroll
            for (int nt = 0; nt < 8; nt++)
                ldm_x2(kf[nt][0], kf[nt][1], sKh + kfb + nt * 8 * AROWB + g * 32);
#pragma unroll
            for (int nt = 0; nt < 8; nt++) mma16816h(sacc[nt], qa[g], kf[nt]);
        }

        // ---- transform + pack P (fp16)
        uint32_t pa[4][4];
#pragma unroll
        for (int nt = 0; nt < 8; nt++) {
            float2 k0p = *(const float2*)(smem + k0off + (nt * 8 + cpair) * 4);
            const int keyc = key_base + nt * 8 + cpair;

            float p0 = score_p(sacc[nt][0], q00, k0p.x, invk, c1);
            float p1 = score_p(sacc[nt][1], q00, k0p.y, invk, c1);
            float p2 = score_p(sacc[nt][2], q01, k0p.x, invk, c1);
            float p3 = score_p(sacc[nt][3], q01, k0p.y, invk, c1);
            if (maskT) {
                if (keyc     > qr0) p0 = 0.0f;
                if (keyc + 1 > qr0) p1 = 0.0f;
                if (keyc     > qr1) p2 = 0.0f;
                if (keyc + 1 > qr1) p3 = 0.0f;
            }
            ls0 += p0 + p1;
            ls1 += p2 + p3;

            const int g = nt >> 1;
            const int rb = (nt & 1) * 2;
            pa[g][rb + 0] = pack_h2(p0, p1);
            pa[g][rb + 1] = pack_h2(p2, p3);
        }

        // ---- O += P V (single pass)
#pragma unroll
        for (int g = 0; g < 4; g++) {
            uint32_t vf[8][2];
#pragma unroll
            for (int dt = 0; dt < 8; dt++)
                ldm_x2t(vf[dt][0], vf[dt][1], sVh + vfb + g * 16 * AROWB + dt * 16);
#pragma unroll
            for (int dt = 0; dt < 8; dt++) mma16816h(O[dt], pa[g], vf[dt]);
        }
    }

    ls0 += __shfl_xor_sync(0xffffffffu, ls0, 1);
    ls0 += __shfl_xor_sync(0xffffffffu, ls0, 2);
    ls1 += __shfl_xor_sync(0xffffffffu, ls1, 1);
    ls1 += __shfl_xor_sync(0xffffffffu, ls1, 2);
    const float n0 = 1.0f / ls0;
    const float n1 = 1.0f / ls1;

    // epilogue: fp16 store for GEMM2
    const size_t o0 = ((size_t)b * T_ + qr0) * C_ + h * 64;
    const size_t o1 = ((size_t)b * T_ + qr1) * C_ + h * 64;
#pragma unroll
    for (int dt = 0; dt < 8; dt++) {
        const int c = dt * 8 + cpair;
        *(uint32_t*)(g_oh + o0 + c) = pack_h2(O[dt][0] * n0, O[dt][1] * n0);
        *(uint32_t*)(g_oh + o1 + c) = pack_h2(O[dt][2] * n1, O[dt][3] * n1);
    }
}

// ---------------- launch ------------------------------------------------------
extern "C" void kernel_launch(void* const* d_in, const int* in_sizes, int n_in,
                              void* d_out, int out_size)
{
    const float* x    = (const float*)d_in[0];
    const float* Wqkv = (const float*)d_in[1];
    const float* Wout = (const float*)d_in[2];
    const float* hyp  = (const float*)d_in[3];
    float* out = (float*)d_out;

    static float* p_qkv = nullptr;
    static __half *p_xh, *p_w1h, *p_w2h, *p_oh;
    if (!p_qkv) {
        cudaGetSymbolAddress((void**)&p_qkv, g_qkv);
        cudaGetSymbolAddress((void**)&p_xh, g_xh);
        cudaGetSymbolAddress((void**)&p_w1h, g_w1h);
        cudaGetSymbolAddress((void**)&p_w2h, g_w2h);
        cudaGetSymbolAddress((void**)&p_oh, g_oh);
        cudaFuncSetAttribute(gemm_hf,
                             cudaFuncAttributeMaxDynamicSharedMemorySize, GSM);
        cudaFuncSetAttribute(attn_mma,
                             cudaFuncAttributeMaxDynamicSharedMemorySize, ATT_SMEM);
    }

    // 0) conversions (all fp16 hi only)
    cvt_h<<<(4096 * 1024 / 4 + 255) / 256, 256>>>(x, p_xh, 4096 * 1024 / 4);
    cvt_h<<<(3072 * 1024 / 4 + 255) / 256, 256>>>(Wqkv, p_w1h, 3072 * 1024 / 4);
    cvt_h<<<(1024 * 1024 / 4 + 255) / 256, 256>>>(Wout, p_w2h, 1024 * 1024 / 4);

    // 1) qkv = x @ W_qkv^T  (single-pass fp16)
    gemm_hf<<<dim3(3072 / 256, 4096 / 128), 256, GSM>>>(
        p_xh, p_w1h, p_qkv, 4096, 3072, 1024);

    // 2) RoPE + fp16 conversion + norms
    rope_split<<<B_ * T_ * H_ / 8, 256>>>(p_qkv, hyp);

    // 3) tensorized attention (single-pass fp16)
    attn_mma<<<dim3(T_ / 128, H_, B_), 256, ATT_SMEM>>>(hyp);

    // 4) out = o @ W_out^T  (single-pass fp16)
    gemm_hf<<<dim3(1024 / 256, 4096 / 128), 256, GSM>>>(
        p_oh, p_w2h, out, 4096, 1024, 1024);
}

// round 16
// speedup vs baseline: 1.9729x; 1.0364x over previous
#include <cuda_runtime.h>
#include <cuda_fp16.h>
#include <math.h>
#include <stdint.h>

#define B_ 4
#define T_ 1024
#define C_ 1024
#define H_ 16
#define HD 64

// ---------------- scratch (static device globals; no allocation) -------------
__device__ float g_q0[(size_t)B_ * H_ * T_];
__device__ float g_k0[(size_t)B_ * H_ * T_];
__device__ __align__(16) __half g_xh[(size_t)4096 * 1024];
__device__ __align__(16) __half g_w1h[(size_t)3072 * 1024];
__device__ __align__(16) __half g_w2h[(size_t)1024 * 1024];
__device__ __align__(16) __half g_oh[(size_t)4096 * 1024];
__device__ __align__(16) __half g_qh[(size_t)4096 * 1024];
__device__ __align__(16) __half g_kh[(size_t)4096 * 1024];
__device__ __align__(16) __half g_vh[(size_t)4096 * 1024];
__device__ __align__(8) float2 g_cs[32768];   // cos/sin table [t][j]

// ---------------- helpers ------------------------------------------------------
__device__ __forceinline__ uint32_t smem_u32(const void* p) {
    uint32_t a;
    asm("{ .reg .u64 t; cvta.to.shared.u64 t, %1; cvt.u32.u64 %0, t; }" : "=r"(a) : "l"(p));
    return a;
}
#define CP_ASYNC16(d, s)  asm volatile("cp.async.cg.shared.global [%0], [%1], 16;" :: "r"(d), "l"(s))
#define CP_COMMIT()       asm volatile("cp.async.commit_group;" ::: "memory")
#define CP_WAIT(n)        asm volatile("cp.async.wait_group %0;" :: "n"(n) : "memory")

__device__ __forceinline__ void ldm_x4(uint32_t& r0, uint32_t& r1, uint32_t& r2, uint32_t& r3,
                                       uint32_t addr) {
    asm volatile("ldmatrix.sync.aligned.m8n8.x4.shared.b16 {%0,%1,%2,%3}, [%4];"
                 : "=r"(r0), "=r"(r1), "=r"(r2), "=r"(r3) : "r"(addr));
}
__device__ __forceinline__ void ldm_x2(uint32_t& r0, uint32_t& r1, uint32_t addr) {
    asm volatile("ldmatrix.sync.aligned.m8n8.x2.shared.b16 {%0,%1}, [%2];"
                 : "=r"(r0), "=r"(r1) : "r"(addr));
}
__device__ __forceinline__ void ldm_x2t(uint32_t& r0, uint32_t& r1, uint32_t addr) {
    asm volatile("ldmatrix.sync.aligned.m8n8.x2.trans.shared.b16 {%0,%1}, [%2];"
                 : "=r"(r0), "=r"(r1) : "r"(addr));
}
__device__ __forceinline__ void mma16816h(float* d, const uint32_t* a, const uint32_t* b) {
    asm volatile("mma.sync.aligned.m16n8k16.row.col.f32.f16.f16.f32 "
                 "{%0,%1,%2,%3}, {%4,%5,%6,%7}, {%8,%9}, {%0,%1,%2,%3};"
                 : "+f"(d[0]), "+f"(d[1]), "+f"(d[2]), "+f"(d[3])
                 : "r"(a[0]), "r"(a[1]), "r"(a[2]), "r"(a[3]), "r"(b[0]), "r"(b[1]));
}
__device__ __forceinline__ uint32_t pack_h2(float x, float y) {
    __half2 h(__float2half(x), __float2half(y));
    return *(uint32_t*)&h;
}

// ---------------- tiny prep kernels --------------------------------------------
__global__ void cvt_h(const float* __restrict__ src, __half* __restrict__ hi, int n4)
{
    int i = blockIdx.x * blockDim.x + threadIdx.x;
    if (i >= n4) return;
    float4 v = ((const float4*)src)[i];
    *(uint2*)(hi + (size_t)i * 4) = make_uint2(pack_h2(v.x, v.y), pack_h2(v.z, v.w));
}
__global__ void build_cs()
{
    int idx = blockIdx.x * 256 + threadIdx.x;   // t*32 + j
    int t = idx >> 5, j = idx & 31;
    float inv = powf(10000.0f, -(float)(2 * j) / 64.0f);
    float fr = (float)t * inv;
    g_cs[idx] = make_float2(cosf(fr), sinf(fr));
}

// ---------------- GEMM core macro-free shared pieces ---------------------------
#define ROWB 80
#define GSTAGE 30720
#define GSM (2 * GSTAGE)

// ---------------- GEMM1 + fused RoPE/split/norm epilogue ----------------------
// A = xh [4096,1024], B = w1h [3072,1024]. Writes q/k/v fp16 + q0/k0.
__global__ __launch_bounds__(256, 1) void gemm_qkv(
    const __half* __restrict__ Ah, const __half* __restrict__ Bh,
    const float* __restrict__ hyp)
{
    const int K = 1024;
    extern __shared__ __align__(128) char smem[];
    const uint32_t sb = smem_u32(smem);
    const int tid = threadIdx.x;
    const int lane = tid & 31, warp = tid >> 5;
    const int wm = warp >> 2, wn = warp & 3;
    const int bm = blockIdx.y * 128, bn = blockIdx.x * 256;
    const int NC = K / 32;

    const int ar = tid >> 2, ac = tid & 3;

    auto issue_stage = [&](int slot, int k0) {
        const uint32_t st = sb + slot * GSTAGE;
        {
            uint32_t d = st + ar * ROWB + ac * 16;
            const size_t s0 = (size_t)(bm + ar) * K + k0 + ac * 8;
            CP_ASYNC16(d, Ah + s0);
            uint32_t d2 = st + (ar + 64) * ROWB + ac * 16;
            const size_t s2 = (size_t)(bm + ar + 64) * K + k0 + ac * 8;
            CP_ASYNC16(d2, Ah + s2);
        }
#pragma unroll
        for (int i = 0; i < 4; i++) {
            int c = tid + i * 256;
            int br = c >> 2, bc = c & 3;
            uint32_t d = st + 10240 + br * ROWB + bc * 16;
            const size_t s0 = (size_t)(bn + br) * K + k0 + bc * 8;
            CP_ASYNC16(d, Bh + s0);
        }
    };

    issue_stage(0, 0);
    CP_COMMIT();

    float acc[32][4] = {};

    const uint32_t aoff = (uint32_t)((wm * 64 + (lane & 15)) * ROWB + (lane >> 4) * 16);
    const uint32_t boff = (uint32_t)(10240 + (wn * 64 + (lane & 7)) * ROWB +
                                     ((lane >> 3) & 1) * 16);

    for (int i = 0; i < NC; i++) {
        if (i > 0) __syncthreads();
        if (i + 1 < NC) { issue_stage((i + 1) & 1, (i + 1) * 32); CP_COMMIT(); CP_WAIT(1); }
        else           { CP_WAIT(0); }
        __syncthreads();

        const uint32_t st = sb + (i & 1) * GSTAGE;

#pragma unroll
        for (int kk = 0; kk < 2; kk++) {
            uint32_t ah[4][4], bh[8][2];
#pragma unroll
            for (int am = 0; am < 4; am++) {
                uint32_t ad = st + aoff + am * 16 * ROWB + kk * 32;
                ldm_x4(ah[am][0], ah[am][1], ah[am][2], ah[am][3], ad);
            }
#pragma unroll
            for (int nt = 0; nt < 8; nt++) {
                uint32_t bd = st + boff + nt * 8 * ROWB + kk * 32;
                ldm_x2(bh[nt][0], bh[nt][1], bd);
            }
#pragma unroll
            for (int am = 0; am < 4; am++)
#pragma unroll
                for (int nt = 0; nt < 8; nt++)
                    mma16816h(acc[am * 8 + nt], ah[am], bh[nt]);
        }
    }

    // ---- fused epilogue ----
    const int er = bm + wm * 64 + (lane >> 2);
    const int jb = (lane & 3) * 2;                 // col-in-head base
    const int type = bn >> 10;                     // 0=q, 1=k, 2=v
    const int h = ((bn & 1023) >> 6) + wn;         // head for this warp

    if (type == 2) {
        // V: plain fp16 store in [B,H,T,hd] layout
#pragma unroll
        for (int am = 0; am < 4; am++) {
            int r0 = er + am * 16, r1 = r0 + 8;
            size_t base0 = ((size_t)((r0 >> 10) * H_ + h) * T_ + (r0 & 1023)) * 64;
            size_t base1 = ((size_t)((r1 >> 10) * H_ + h) * T_ + (r1 & 1023)) * 64;
#pragma unroll
            for (int nt = 0; nt < 8; nt++) {
                float* d = acc[am * 8 + nt];
                *(uint32_t*)(g_vh + base0 + jb + nt * 8) = pack_h2(d[0], d[1]);
                *(uint32_t*)(g_vh + base1 + jb + nt * 8) = pack_h2(d[2], d[3]);
            }
        }
    } else {
        __half* dst = (type == 0) ? g_qh : g_kh;
        float* nrm  = (type == 0) ? g_q0 : g_k0;
        const float kc = hyp[h];
#pragma unroll
        for (int am = 0; am < 4; am++) {
            int r0 = er + am * 16, r1 = r0 + 8;
            int t0 = r0 & 1023, t1 = r1 & 1023;
            size_t row0 = (size_t)((r0 >> 10) * H_ + h) * T_ + t0;
            size_t row1 = (size_t)((r1 >> 10) * H_ + h) * T_ + t1;
            size_t base0 = row0 * 64, base1 = row1 * 64;
            float ss0 = 0.0f, ss1 = 0.0f;
#pragma unroll
            for (int nt = 0; nt < 4; nt++) {
                float* a = acc[am * 8 + nt];       // cols j, j+1
                float* c = acc[am * 8 + nt + 4];   // cols j+32, j+33
                int j = jb + nt * 8;
                float2 cA0 = g_cs[t0 * 32 + j];
                float2 cA1 = g_cs[t0 * 32 + j + 1];
                float2 cB0 = g_cs[t1 * 32 + j];
                float2 cB1 = g_cs[t1 * 32 + j + 1];
                // row0
                float o1  = a[0] * cA0.x + c[0] * cA0.y;
                float o2  = -a[0] * cA0.y + c[0] * cA0.x;
                float o1b = a[1] * cA1.x + c[1] * cA1.y;
                float o2b = -a[1] * cA1.y + c[1] * cA1.x;
                ss0 += a[0] * a[0] + c[0] * c[0] + a[1] * a[1] + c[1] * c[1];
                *(uint32_t*)(dst + base0 + j)      = pack_h2(o1, o1b);
                *(uint32_t*)(dst + base0 + j + 32) = pack_h2(o2, o2b);
                // row1
                float p1  = a[2] * cB0.x + c[2] * cB0.y;
                float p2  = -a[2] * cB0.y + c[2] * cB0.x;
                float p1b = a[3] * cB1.x + c[3] * cB1.y;
                float p2b = -a[3] * cB1.y + c[3] * cB1.x;
                ss1 += a[2] * a[2] + c[2] * c[2] + a[3] * a[3] + c[3] * c[3];
                *(uint32_t*)(dst + base1 + j)      = pack_h2(p1, p1b);
                *(uint32_t*)(dst + base1 + j + 32) = pack_h2(p2, p2b);
            }
            ss0 += __shfl_xor_sync(0xffffffffu, ss0, 1);
            ss0 += __shfl_xor_sync(0xffffffffu, ss0, 2);
            ss1 += __shfl_xor_sync(0xffffffffu, ss1, 1);
            ss1 += __shfl_xor_sync(0xffffffffu, ss1, 2);
            if ((lane & 3) == 0) {
                nrm[row0] = sqrtf(kc + ss0);
                nrm[row1] = sqrtf(kc + ss1);
            }
        }
    }
}

// ---------------- GEMM2: single-pass fp16 (unchanged) --------------------------
__global__ __launch_bounds__(256, 1) void gemm_hf(
    const __half* __restrict__ Ah, const __half* __restrict__ Bh,
    float* __restrict__ C, int M, int N, int K)
{
    extern __shared__ __align__(128) char smem[];
    const uint32_t sb = smem_u32(smem);
    const int tid = threadIdx.x;
    const int lane = tid & 31, warp = tid >> 5;
    const int wm = warp >> 2, wn = warp & 3;
    const int bm = blockIdx.y * 128, bn = blockIdx.x * 256;
    const int NC = K / 32;

    const int ar = tid >> 2, ac = tid & 3;

    auto issue_stage = [&](int slot, int k0) {
        const uint32_t st = sb + slot * GSTAGE;
        {
            uint32_t d = st + ar * ROWB + ac * 16;
            const size_t s0 = (size_t)(bm + ar) * K + k0 + ac * 8;
            CP_ASYNC16(d, Ah + s0);
            uint32_t d2 = st + (ar + 64) * ROWB + ac * 16;
            const size_t s2 = (size_t)(bm + ar + 64) * K + k0 + ac * 8;
            CP_ASYNC16(d2, Ah + s2);
        }
#pragma unroll
        for (int i = 0; i < 4; i++) {
            int c = tid + i * 256;
            int br = c >> 2, bc = c & 3;
            uint32_t d = st + 10240 + br * ROWB + bc * 16;
            const size_t s0 = (size_t)(bn + br) * K + k0 + bc * 8;
            CP_ASYNC16(d, Bh + s0);
        }
    };

    issue_stage(0, 0);
    CP_COMMIT();

    float acc[32][4] = {};

    const uint32_t aoff = (uint32_t)((wm * 64 + (lane & 15)) * ROWB + (lane >> 4) * 16);
    const uint32_t boff = (uint32_t)(10240 + (wn * 64 + (lane & 7)) * ROWB +
                                     ((lane >> 3) & 1) * 16);

    for (int i = 0; i < NC; i++) {
        if (i > 0) __syncthreads();
        if (i + 1 < NC) { issue_stage((i + 1) & 1, (i + 1) * 32); CP_COMMIT(); CP_WAIT(1); }
        else           { CP_WAIT(0); }
        __syncthreads();

        const uint32_t st = sb + (i & 1) * GSTAGE;

#pragma unroll
        for (int kk = 0; kk < 2; kk++) {
            uint32_t ah[4][4], bh[8][2];
#pragma unroll
            for (int am = 0; am < 4; am++) {
                uint32_t ad = st + aoff + am * 16 * ROWB + kk * 32;
                ldm_x4(ah[am][0], ah[am][1], ah[am][2], ah[am][3], ad);
            }
#pragma unroll
            for (int nt = 0; nt < 8; nt++) {
                uint32_t bd = st + boff + nt * 8 * ROWB + kk * 32;
                ldm_x2(bh[nt][0], bh[nt][1], bd);
            }
#pragma unroll
            for (int am = 0; am < 4; am++)
#pragma unroll
                for (int nt = 0; nt < 8; nt++)
                    mma16816h(acc[am * 8 + nt], ah[am], bh[nt]);
        }
    }

    const int er = bm + wm * 64 + (lane >> 2);
    const int ec = bn + wn * 64 + (lane & 3) * 2;
#pragma unroll
    for (int am = 0; am < 4; am++)
#pragma unroll
        for (int nt = 0; nt < 8; nt++) {
            float* d = acc[am * 8 + nt];
            int r = er + am * 16;
            int c = ec + nt * 8;
            *(float2*)(C + (size_t)r * N + c) = make_float2(d[0], d[1]);
            *(float2*)(C + (size_t)(r + 8) * N + c) = make_float2(d[2], d[3]);
        }
}

// ---------------- per-score hyperbolic transform (4 MUFU) ---------------------
__device__ __forceinline__ float score_p(float s, float q0, float k0,
                                         float invk, float c1) {
    float inner = s - q0 * k0;
    float arg = fmaxf(-inner * invk, 1.000001f);
    float t = fmaf(arg, arg, -1.0f);
    float sq; asm("sqrt.approx.f32 %0, %1;" : "=f"(sq) : "f"(t));
    float y = arg + sq;
    float lg; asm("lg2.approx.f32 %0, %1;" : "=f"(lg) : "f"(y));
    float u = fmaf(c1, lg, 1e-6f);
    float w; asm("rcp.approx.f32 %0, %1;" : "=f"(w) : "f"(u));
    w = fminf(w, 60.0f);
    float p; asm("ex2.approx.f32 %0, %1;" : "=f"(p) : "f"(w * 1.44269504f));
    return p;
}

// ---------------- tensorized attention (unchanged from R15) -------------------
#define AROWB 144
#define SQH 0
#define SKV 18432
#define KVSTG 18432
#define SK0A 55296
#define ATT_SMEM 55808

__global__ __launch_bounds__(256, 1) void attn_mma(const float* __restrict__ hyp)
{
    extern __shared__ __align__(128) char smem[];
    const uint32_t sb = smem_u32(smem);
    const int tid = threadIdx.x;
    const int lane = tid & 31, warp = tid >> 5;
    const int qt = (int)gridDim.x - 1 - (int)blockIdx.x;
    const int h = blockIdx.y, b = blockIdx.z;
    const size_t bh = (size_t)b * H_ + h;
    const size_t qbase = (bh * T_ + (size_t)qt * 128) * HD;
    const size_t kvbase = bh * T_ * HD;
    const float* k0g = g_k0 + bh * T_;

    const float kc   = hyp[h];
    const float invk = 1.0f / kc;
    const float c1   = sqrtf(kc) * 0.69314718056f;

    const int ar0 = tid >> 3, ac0 = tid & 7;
    const int ar1 = (tid + 256) >> 3;

#pragma unroll
    for (int i = 0; i < 4; i++) {
        int ch = tid + i * 256;
        int row = ch >> 3, cc = ch & 7;
        CP_ASYNC16(sb + SQH + row * AROWB + cc * 16, g_qh + qbase + row * 64 + cc * 8);
    }
    CP_COMMIT();

    auto issue_kv = [&](int slot, int st) {
        const uint32_t sk = sb + SKV + slot * KVSTG;
        const size_t tb = kvbase + (size_t)st * 64 * 64;
        uint32_t d0 = sk + ar0 * AROWB + ac0 * 16;
        const size_t s0 = tb + ar0 * 64 + ac0 * 8;
        CP_ASYNC16(d0,        g_kh + s0);
        CP_ASYNC16(d0 + 9216, g_vh + s0);
        uint32_t d1 = sk + ar1 * AROWB + ac0 * 16;
        const size_t s1 = tb + ar1 * 64 + ac0 * 8;
        CP_ASYNC16(d1,        g_kh + s1);
        CP_ASYNC16(d1 + 9216, g_vh + s1);
        if (tid < 16) CP_ASYNC16(sb + SK0A + slot * 256 + tid * 16,
                                 k0g + st * 64 + tid * 4);
    };

    const int ntile = 2 * qt + 2;
    issue_kv(0, 0);
    CP_COMMIT();

    CP_WAIT(1);
    __syncthreads();
    uint32_t qa[4][4];
    const uint32_t qoff = (uint32_t)((warp * 16 + (lane & 15)) * AROWB + (lane >> 4) * 16);
#pragma unroll
    for (int g = 0; g < 4; g++)
        ldm_x4(qa[g][0], qa[g][1], qa[g][2], qa[g][3], sb + SQH + qoff + g * 32);

    const int r_in  = lane >> 2;
    const int cpair = (lane & 3) * 2;
    const int qr0 = qt * 128 + warp * 16 + r_in;
    const int qr1 = qr0 + 8;
    const float q00 = g_q0[bh * T_ + qr0];
    const float q01 = g_q0[bh * T_ + qr1];

    float O[8][4] = {};
    float ls0 = 0.0f, ls1 = 0.0f;

    const uint32_t kfb = (uint32_t)((lane & 7) * AROWB + ((lane >> 3) & 1) * 16);
    const uint32_t vfb = (uint32_t)((lane & 15) * AROWB);

    for (int st = 0; st < ntile; st++) {
        __syncthreads();
        if (st + 1 < ntile) {
            issue_kv((st + 1) & 1, st + 1);
            CP_COMMIT();
        }
        if (st + 1 < ntile) { CP_WAIT(1); } else { CP_WAIT(0); }
        __syncthreads();

        const uint32_t sKh = sb + SKV + (st & 1) * KVSTG;
        const uint32_t sVh = sKh + 9216;
        const uint32_t k0off = SK0A + (st & 1) * 256;

        const bool maskT = (st >= 2 * qt);
        const int key_base = st * 64;

        float sacc[8][4] = {};
#pragma unroll
        for (int g = 0; g < 4; g++) {
            uint32_t kf[8][2];
#pragma unroll
            for (int nt = 0; nt < 8; nt++)
                ldm_x2(kf[nt][0], kf[nt][1], sKh + kfb + nt * 8 * AROWB + g * 32);
#pragma unroll
            for (int nt = 0; nt < 8; nt++) mma16816h(sacc[nt], qa[g], kf[nt]);
        }

        uint32_t pa[4][4];
#pragma unroll
        for (int nt = 0; nt < 8; nt++) {
            float2 k0p = *(const float2*)(smem + k0off + (nt * 8 + cpair) * 4);
            const int keyc = key_base + nt * 8 + cpair;

            float p0 = score_p(sacc[nt][0], q00, k0p.x, invk, c1);
            float p1 = score_p(sacc[nt][1], q00, k0p.y, invk, c1);
            float p2 = score_p(sacc[nt][2], q01, k0p.x, invk, c1);
            float p3 = score_p(sacc[nt][3], q01, k0p.y, invk, c1);
            if (maskT) {
                if (keyc     > qr0) p0 = 0.0f;
                if (keyc + 1 > qr0) p1 = 0.0f;
                if (keyc     > qr1) p2 = 0.0f;
                if (keyc + 1 > qr1) p3 = 0.0f;
            }
            ls0 += p0 + p1;
            ls1 += p2 + p3;

            const int g = nt >> 1;
            const int rb = (nt & 1) * 2;
            pa[g][rb + 0] = pack_h2(p0, p1);
            pa[g][rb + 1] = pack_h2(p2, p3);
        }

#pragma unroll
        for (int g = 0; g < 4; g++) {
            uint32_t vf[8][2];
#pragma unroll
            for (int dt = 0; dt < 8; dt++)
                ldm_x2t(vf[dt][0], vf[dt][1], sVh + vfb + g * 16 * AROWB + dt * 16);
#pragma unroll
            for (int dt = 0; dt < 8; dt++) mma16816h(O[dt], pa[g], vf[dt]);
        }
    }

    ls0 += __shfl_xor_sync(0xffffffffu, ls0, 1);
    ls0 += __shfl_xor_sync(0xffffffffu, ls0, 2);
    ls1 += __shfl_xor_sync(0xffffffffu, ls1, 1);
    ls1 += __shfl_xor_sync(0xffffffffu, ls1, 2);
    const float n0 = 1.0f / ls0;
    const float n1 = 1.0f / ls1;

    const size_t o0 = ((size_t)b * T_ + qr0) * C_ + h * 64;
    const size_t o1 = ((size_t)b * T_ + qr1) * C_ + h * 64;
#pragma unroll
    for (int dt = 0; dt < 8; dt++) {
        const int c = dt * 8 + cpair;
        *(uint32_t*)(g_oh + o0 + c) = pack_h2(O[dt][0] * n0, O[dt][1] * n0);
        *(uint32_t*)(g_oh + o1 + c) = pack_h2(O[dt][2] * n1, O[dt][3] * n1);
    }
}

// ---------------- launch ------------------------------------------------------
extern "C" void kernel_launch(void* const* d_in, const int* in_sizes, int n_in,
                              void* d_out, int out_size)
{
    const float* x    = (const float*)d_in[0];
    const float* Wqkv = (const float*)d_in[1];
    const float* Wout = (const float*)d_in[2];
    const float* hyp  = (const float*)d_in[3];
    float* out = (float*)d_out;

    static __half *p_xh = nullptr, *p_w1h, *p_w2h, *p_oh;
    if (!p_xh) {
        cudaGetSymbolAddress((void**)&p_xh, g_xh);
        cudaGetSymbolAddress((void**)&p_w1h, g_w1h);
        cudaGetSymbolAddress((void**)&p_w2h, g_w2h);
        cudaGetSymbolAddress((void**)&p_oh, g_oh);
        cudaFuncSetAttribute(gemm_qkv,
                             cudaFuncAttributeMaxDynamicSharedMemorySize, GSM);
        cudaFuncSetAttribute(gemm_hf,
                             cudaFuncAttributeMaxDynamicSharedMemorySize, GSM);
        cudaFuncSetAttribute(attn_mma,
                             cudaFuncAttributeMaxDynamicSharedMemorySize, ATT_SMEM);
    }

    // 0) conversions + cos/sin table
    build_cs<<<128, 256>>>();
    cvt_h<<<(4096 * 1024 / 4 + 255) / 256, 256>>>(x, p_xh, 4096 * 1024 / 4);
    cvt_h<<<(3072 * 1024 / 4 + 255) / 256, 256>>>(Wqkv, p_w1h, 3072 * 1024 / 4);
    cvt_h<<<(1024 * 1024 / 4 + 255) / 256, 256>>>(Wout, p_w2h, 1024 * 1024 / 4);

    // 1) qkv = x @ W_qkv^T with fused RoPE/split/norm epilogue
    gemm_qkv<<<dim3(3072 / 256, 4096 / 128), 256, GSM>>>(p_xh, p_w1h, hyp);

    // 2) tensorized attention (single-pass fp16)
    attn_mma<<<dim3(T_ / 128, H_, B_), 256, ATT_SMEM>>>(hyp);

    // 3) out = o @ W_out^T
    gemm_hf<<<dim3(1024 / 256, 4096 / 128), 256, GSM>>>(
        p_oh, p_w2h, out, 4096, 1024, 1024);
}

// round 17
// speedup vs baseline: 2.1561x; 1.0929x over previous
#include <cuda_runtime.h>
#include <cuda_fp16.h>
#include <math.h>
#include <stdint.h>

#define B_ 4
#define T_ 1024
#define C_ 1024
#define H_ 16
#define HD 64

// ---------------- scratch (static device globals; no allocation) -------------
__device__ float g_q0[(size_t)B_ * H_ * T_];
__device__ float g_k0[(size_t)B_ * H_ * T_];
__device__ __align__(16) __half g_xh[(size_t)4096 * 1024];
__device__ __align__(16) __half g_w1h[(size_t)3072 * 1024];
__device__ __align__(16) __half g_w2h[(size_t)1024 * 1024];
__device__ __align__(16) __half g_oh[(size_t)4096 * 1024];
__device__ __align__(16) __half g_qh[(size_t)4096 * 1024];
__device__ __align__(16) __half g_kh[(size_t)4096 * 1024];
__device__ __align__(16) __half g_vh[(size_t)4096 * 1024];
__device__ __align__(8) float2 g_cs[32768];   // cos/sin table [t][j]

// ---------------- helpers ------------------------------------------------------
__device__ __forceinline__ uint32_t smem_u32(const void* p) {
    uint32_t a;
    asm("{ .reg .u64 t; cvta.to.shared.u64 t, %1; cvt.u32.u64 %0, t; }" : "=r"(a) : "l"(p));
    return a;
}
#define CP_ASYNC16(d, s)  asm volatile("cp.async.cg.shared.global [%0], [%1], 16;" :: "r"(d), "l"(s))
#define CP_COMMIT()       asm volatile("cp.async.commit_group;" ::: "memory")
#define CP_WAIT(n)        asm volatile("cp.async.wait_group %0;" :: "n"(n) : "memory")

__device__ __forceinline__ void ldm_x4(uint32_t& r0, uint32_t& r1, uint32_t& r2, uint32_t& r3,
                                       uint32_t addr) {
    asm volatile("ldmatrix.sync.aligned.m8n8.x4.shared.b16 {%0,%1,%2,%3}, [%4];"
                 : "=r"(r0), "=r"(r1), "=r"(r2), "=r"(r3) : "r"(addr));
}
__device__ __forceinline__ void ldm_x2(uint32_t& r0, uint32_t& r1, uint32_t addr) {
    asm volatile("ldmatrix.sync.aligned.m8n8.x2.shared.b16 {%0,%1}, [%2];"
                 : "=r"(r0), "=r"(r1) : "r"(addr));
}
__device__ __forceinline__ void ldm_x2t(uint32_t& r0, uint32_t& r1, uint32_t addr) {
    asm volatile("ldmatrix.sync.aligned.m8n8.x2.trans.shared.b16 {%0,%1}, [%2];"
                 : "=r"(r0), "=r"(r1) : "r"(addr));
}
__device__ __forceinline__ void mma16816h(float* d, const uint32_t* a, const uint32_t* b) {
    asm volatile("mma.sync.aligned.m16n8k16.row.col.f32.f16.f16.f32 "
                 "{%0,%1,%2,%3}, {%4,%5,%6,%7}, {%8,%9}, {%0,%1,%2,%3};"
                 : "+f"(d[0]), "+f"(d[1]), "+f"(d[2]), "+f"(d[3])
                 : "r"(a[0]), "r"(a[1]), "r"(a[2]), "r"(a[3]), "r"(b[0]), "r"(b[1]));
}
__device__ __forceinline__ uint32_t pack_h2(float x, float y) {
    __half2 h(__float2half(x), __float2half(y));
    return *(uint32_t*)&h;
}

// ---------------- tiny prep kernels --------------------------------------------
__global__ void cvt_h(const float* __restrict__ src, __half* __restrict__ hi, int n4)
{
    int i = blockIdx.x * blockDim.x + threadIdx.x;
    if (i >= n4) return;
    float4 v = ((const float4*)src)[i];
    *(uint2*)(hi + (size_t)i * 4) = make_uint2(pack_h2(v.x, v.y), pack_h2(v.z, v.w));
}
__global__ void build_cs()
{
    int idx = blockIdx.x * 256 + threadIdx.x;
    int t = idx >> 5, j = idx & 31;
    float inv = powf(10000.0f, -(float)(2 * j) / 64.0f);
    float fr = (float)t * inv;
    g_cs[idx] = make_float2(cosf(fr), sinf(fr));
}

// ---------------- GEMM: K-chunk 64, single-pass fp16 --------------------------
// CTA 128x256x64, 8 warps (64x64). Stage: A 0 (18432), B 18432 (36864) = 55296.
#define ROWB2 144
#define GSTAGE 55296
#define GSM (2 * GSTAGE)

// shared mainloop body macro-free: implemented twice (plain / fused-qkv epilogue)

__global__ __launch_bounds__(256, 1) void gemm_qkv(
    const __half* __restrict__ Ah, const __half* __restrict__ Bh,
    const float* __restrict__ hyp)
{
    const int K = 1024;
    extern __shared__ __align__(128) char smem[];
    const uint32_t sb = smem_u32(smem);
    const int tid = threadIdx.x;
    const int lane = tid & 31, warp = tid >> 5;
    const int wm = warp >> 2, wn = warp & 3;
    const int bm = blockIdx.y * 128, bn = blockIdx.x * 256;
    const int NC = K / 64;

    auto issue_stage = [&](int slot, int k0) {
        const uint32_t st = sb + slot * GSTAGE;
#pragma unroll
        for (int i = 0; i < 4; i++) {
            int ch = tid + i * 256;
            int row = ch >> 3, col = ch & 7;
            CP_ASYNC16(st + row * ROWB2 + col * 16,
                       Ah + (size_t)(bm + row) * K + k0 + col * 8);
        }
#pragma unroll
        for (int i = 0; i < 8; i++) {
            int ch = tid + i * 256;
            int row = ch >> 3, col = ch & 7;
            CP_ASYNC16(st + 18432 + row * ROWB2 + col * 16,
                       Bh + (size_t)(bn + row) * K + k0 + col * 8);
        }
    };

    issue_stage(0, 0);
    CP_COMMIT();

    float acc[32][4] = {};

    const uint32_t aoff = (uint32_t)((wm * 64 + (lane & 15)) * ROWB2 + (lane >> 4) * 16);
    const uint32_t boff = (uint32_t)(18432 + (wn * 64 + (lane & 7)) * ROWB2 +
                                     ((lane >> 3) & 1) * 16);

    for (int i = 0; i < NC; i++) {
        if (i > 0) __syncthreads();
        if (i + 1 < NC) { issue_stage((i + 1) & 1, (i + 1) * 64); CP_COMMIT(); CP_WAIT(1); }
        else           { CP_WAIT(0); }
        __syncthreads();

        const uint32_t st = sb + (i & 1) * GSTAGE;

#pragma unroll
        for (int kk = 0; kk < 4; kk++) {
            uint32_t ah[4][4], bh[8][2];
#pragma unroll
            for (int am = 0; am < 4; am++)
                ldm_x4(ah[am][0], ah[am][1], ah[am][2], ah[am][3],
                       st + aoff + am * 16 * ROWB2 + kk * 32);
#pragma unroll
            for (int nt = 0; nt < 8; nt++)
                ldm_x2(bh[nt][0], bh[nt][1], st + boff + nt * 8 * ROWB2 + kk * 32);
#pragma unroll
            for (int am = 0; am < 4; am++)
#pragma unroll
                for (int nt = 0; nt < 8; nt++)
                    mma16816h(acc[am * 8 + nt], ah[am], bh[nt]);
        }
    }

    // ---- fused RoPE/split/norm epilogue ----
    const int er = bm + wm * 64 + (lane >> 2);
    const int jb = (lane & 3) * 2;
    const int type = bn >> 10;                     // 0=q, 1=k, 2=v
    const int h = ((bn & 1023) >> 6) + wn;

    if (type == 2) {
#pragma unroll
        for (int am = 0; am < 4; am++) {
            int r0 = er + am * 16, r1 = r0 + 8;
            size_t base0 = ((size_t)((r0 >> 10) * H_ + h) * T_ + (r0 & 1023)) * 64;
            size_t base1 = ((size_t)((r1 >> 10) * H_ + h) * T_ + (r1 & 1023)) * 64;
#pragma unroll
            for (int nt = 0; nt < 8; nt++) {
                float* d = acc[am * 8 + nt];
                *(uint32_t*)(g_vh + base0 + jb + nt * 8) = pack_h2(d[0], d[1]);
                *(uint32_t*)(g_vh + base1 + jb + nt * 8) = pack_h2(d[2], d[3]);
            }
        }
    } else {
        __half* dst = (type == 0) ? g_qh : g_kh;
        float* nrm  = (type == 0) ? g_q0 : g_k0;
        const float kc = hyp[h];
#pragma unroll
        for (int am = 0; am < 4; am++) {
            int r0 = er + am * 16, r1 = r0 + 8;
            int t0 = r0 & 1023, t1 = r1 & 1023;
            size_t row0 = (size_t)((r0 >> 10) * H_ + h) * T_ + t0;
            size_t row1 = (size_t)((r1 >> 10) * H_ + h) * T_ + t1;
            size_t base0 = row0 * 64, base1 = row1 * 64;
            float ss0 = 0.0f, ss1 = 0.0f;
#pragma unroll
            for (int nt = 0; nt < 4; nt++) {
                float* a = acc[am * 8 + nt];
                float* c = acc[am * 8 + nt + 4];
                int j = jb + nt * 8;
                float2 cA0 = g_cs[t0 * 32 + j];
                float2 cA1 = g_cs[t0 * 32 + j + 1];
                float2 cB0 = g_cs[t1 * 32 + j];
                float2 cB1 = g_cs[t1 * 32 + j + 1];
                float o1  = a[0] * cA0.x + c[0] * cA0.y;
                float o2  = -a[0] * cA0.y + c[0] * cA0.x;
                float o1b = a[1] * cA1.x + c[1] * cA1.y;
                float o2b = -a[1] * cA1.y + c[1] * cA1.x;
                ss0 += a[0] * a[0] + c[0] * c[0] + a[1] * a[1] + c[1] * c[1];
                *(uint32_t*)(dst + base0 + j)      = pack_h2(o1, o1b);
                *(uint32_t*)(dst + base0 + j + 32) = pack_h2(o2, o2b);
                float p1  = a[2] * cB0.x + c[2] * cB0.y;
                float p2  = -a[2] * cB0.y + c[2] * cB0.x;
                float p1b = a[3] * cB1.x + c[3] * cB1.y;
                float p2b = -a[3] * cB1.y + c[3] * cB1.x;
                ss1 += a[2] * a[2] + c[2] * c[2] + a[3] * a[3] + c[3] * c[3];
                *(uint32_t*)(dst + base1 + j)      = pack_h2(p1, p1b);
                *(uint32_t*)(dst + base1 + j + 32) = pack_h2(p2, p2b);
            }
            ss0 += __shfl_xor_sync(0xffffffffu, ss0, 1);
            ss0 += __shfl_xor_sync(0xffffffffu, ss0, 2);
            ss1 += __shfl_xor_sync(0xffffffffu, ss1, 1);
            ss1 += __shfl_xor_sync(0xffffffffu, ss1, 2);
            if ((lane & 3) == 0) {
                nrm[row0] = sqrtf(kc + ss0);
                nrm[row1] = sqrtf(kc + ss1);
            }
        }
    }
}

__global__ __launch_bounds__(256, 1) void gemm_hf(
    const __half* __restrict__ Ah, const __half* __restrict__ Bh,
    float* __restrict__ C, int M, int N, int K)
{
    extern __shared__ __align__(128) char smem[];
    const uint32_t sb = smem_u32(smem);
    const int tid = threadIdx.x;
    const int lane = tid & 31, warp = tid >> 5;
    const int wm = warp >> 2, wn = warp & 3;
    const int bm = blockIdx.y * 128, bn = blockIdx.x * 256;
    const int NC = K / 64;

    auto issue_stage = [&](int slot, int k0) {
        const uint32_t st = sb + slot * GSTAGE;
#pragma unroll
        for (int i = 0; i < 4; i++) {
            int ch = tid + i * 256;
            int row = ch >> 3, col = ch & 7;
            CP_ASYNC16(st + row * ROWB2 + col * 16,
                       Ah + (size_t)(bm + row) * K + k0 + col * 8);
        }
#pragma unroll
        for (int i = 0; i < 8; i++) {
            int ch = tid + i * 256;
            int row = ch >> 3, col = ch & 7;
            CP_ASYNC16(st + 18432 + row * ROWB2 + col * 16,
                       Bh + (size_t)(bn + row) * K + k0 + col * 8);
        }
    };

    issue_stage(0, 0);
    CP_COMMIT();

    float acc[32][4] = {};

    const uint32_t aoff = (uint32_t)((wm * 64 + (lane & 15)) * ROWB2 + (lane >> 4) * 16);
    const uint32_t boff = (uint32_t)(18432 + (wn * 64 + (lane & 7)) * ROWB2 +
                                     ((lane >> 3) & 1) * 16);

    for (int i = 0; i < NC; i++) {
        if (i > 0) __syncthreads();
        if (i + 1 < NC) { issue_stage((i + 1) & 1, (i + 1) * 64); CP_COMMIT(); CP_WAIT(1); }
        else           { CP_WAIT(0); }
        __syncthreads();

        const uint32_t st = sb + (i & 1) * GSTAGE;

#pragma unroll
        for (int kk = 0; kk < 4; kk++) {
            uint32_t ah[4][4], bh[8][2];
#pragma unroll
            for (int am = 0; am < 4; am++)
                ldm_x4(ah[am][0], ah[am][1], ah[am][2], ah[am][3],
                       st + aoff + am * 16 * ROWB2 + kk * 32);
#pragma unroll
            for (int nt = 0; nt < 8; nt++)
                ldm_x2(bh[nt][0], bh[nt][1], st + boff + nt * 8 * ROWB2 + kk * 32);
#pragma unroll
            for (int am = 0; am < 4; am++)
#pragma unroll
                for (int nt = 0; nt < 8; nt++)
                    mma16816h(acc[am * 8 + nt], ah[am], bh[nt]);
        }
    }

    const int er = bm + wm * 64 + (lane >> 2);
    const int ec = bn + wn * 64 + (lane & 3) * 2;
#pragma unroll
    for (int am = 0; am < 4; am++)
#pragma unroll
        for (int nt = 0; nt < 8; nt++) {
            float* d = acc[am * 8 + nt];
            int r = er + am * 16;
            int c = ec + nt * 8;
            *(float2*)(C + (size_t)r * N + c) = make_float2(d[0], d[1]);
            *(float2*)(C + (size_t)(r + 8) * N + c) = make_float2(d[2], d[3]);
        }
}

// ---------------- per-score hyperbolic transform (4 MUFU) ---------------------
__device__ __forceinline__ float score_p(float s, float q0, float k0,
                                         float invk, float c1) {
    float inner = s - q0 * k0;
    float arg = fmaxf(-inner * invk, 1.000001f);
    float t = fmaf(arg, arg, -1.0f);
    float sq; asm("sqrt.approx.f32 %0, %1;" : "=f"(sq) : "f"(t));
    float y = arg + sq;
    float lg; asm("lg2.approx.f32 %0, %1;" : "=f"(lg) : "f"(y));
    float u = fmaf(c1, lg, 1e-6f);
    float w; asm("rcp.approx.f32 %0, %1;" : "=f"(w) : "f"(u));
    w = fminf(w, 60.0f);
    float p; asm("ex2.approx.f32 %0, %1;" : "=f"(p) : "f"(w * 1.44269504f));
    return p;
}

// ---------------- tensorized attention (unchanged from R15) -------------------
#define AROWB 144
#define SQH 0
#define SKV 18432
#define KVSTG 18432
#define SK0A 55296
#define ATT_SMEM 55808

__global__ __launch_bounds__(256, 1) void attn_mma(const float* __restrict__ hyp)
{
    extern __shared__ __align__(128) char smem[];
    const uint32_t sb = smem_u32(smem);
    const int tid = threadIdx.x;
    const int lane = tid & 31, warp = tid >> 5;
    const int qt = (int)gridDim.x - 1 - (int)blockIdx.x;
    const int h = blockIdx.y, b = blockIdx.z;
    const size_t bh = (size_t)b * H_ + h;
    const size_t qbase = (bh * T_ + (size_t)qt * 128) * HD;
    const size_t kvbase = bh * T_ * HD;
    const float* k0g = g_k0 + bh * T_;

    const float kc   = hyp[h];
    const float invk = 1.0f / kc;
    const float c1   = sqrtf(kc) * 0.69314718056f;

    const int ar0 = tid >> 3, ac0 = tid & 7;
    const int ar1 = (tid + 256) >> 3;

#pragma unroll
    for (int i = 0; i < 4; i++) {
        int ch = tid + i * 256;
        int row = ch >> 3, cc = ch & 7;
        CP_ASYNC16(sb + SQH + row * AROWB + cc * 16, g_qh + qbase + row * 64 + cc * 8);
    }
    CP_COMMIT();

    auto issue_kv = [&](int slot, int st) {
        const uint32_t sk = sb + SKV + slot * KVSTG;
        const size_t tb = kvbase + (size_t)st * 64 * 64;
        uint32_t d0 = sk + ar0 * AROWB + ac0 * 16;
        const size_t s0 = tb + ar0 * 64 + ac0 * 8;
        CP_ASYNC16(d0,        g_kh + s0);
        CP_ASYNC16(d0 + 9216, g_vh + s0);
        uint32_t d1 = sk + ar1 * AROWB + ac0 * 16;
        const size_t s1 = tb + ar1 * 64 + ac0 * 8;
        CP_ASYNC16(d1,        g_kh + s1);
        CP_ASYNC16(d1 + 9216, g_vh + s1);
        if (tid < 16) CP_ASYNC16(sb + SK0A + slot * 256 + tid * 16,
                                 k0g + st * 64 + tid * 4);
    };

    const int ntile = 2 * qt + 2;
    issue_kv(0, 0);
    CP_COMMIT();

    CP_WAIT(1);
    __syncthreads();
    uint32_t qa[4][4];
    const uint32_t qoff = (uint32_t)((warp * 16 + (lane & 15)) * AROWB + (lane >> 4) * 16);
#pragma unroll
    for (int g = 0; g < 4; g++)
        ldm_x4(qa[g][0], qa[g][1], qa[g][2], qa[g][3], sb + SQH + qoff + g * 32);

    const int r_in  = lane >> 2;
    const int cpair = (lane & 3) * 2;
    const int qr0 = qt * 128 + warp * 16 + r_in;
    const int qr1 = qr0 + 8;
    const float q00 = g_q0[bh * T_ + qr0];
    const float q01 = g_q0[bh * T_ + qr1];

    float O[8][4] = {};
    float ls0 = 0.0f, ls1 = 0.0f;

    const uint32_t kfb = (uint32_t)((lane & 7) * AROWB + ((lane >> 3) & 1) * 16);
    const uint32_t vfb = (uint32_t)((lane & 15) * AROWB);

    for (int st = 0; st < ntile; st++) {
        __syncthreads();
        if (st + 1 < ntile) {
            issue_kv((st + 1) & 1, st + 1);
            CP_COMMIT();
        }
        if (st + 1 < ntile) { CP_WAIT(1); } else { CP_WAIT(0); }
        __syncthreads();

        const uint32_t sKh = sb + SKV + (st & 1) * KVSTG;
        const uint32_t sVh = sKh + 9216;
        const uint32_t k0off = SK0A + (st & 1) * 256;

        const bool maskT = (st >= 2 * qt);
        const int key_base = st * 64;

        float sacc[8][4] = {};
#pragma unroll
        for (int g = 0; g < 4; g++) {
            uint32_t kf[8][2];
#pragma unroll
            for (int nt = 0; nt < 8; nt++)
                ldm_x2(kf[nt][0], kf[nt][1], sKh + kfb + nt * 8 * AROWB + g * 32);
#pragma unroll
            for (int nt = 0; nt < 8; nt++) mma16816h(sacc[nt], qa[g], kf[nt]);
        }

        uint32_t pa[4][4];
#pragma unroll
        for (int nt = 0; nt < 8; nt++) {
            float2 k0p = *(const float2*)(smem + k0off + (nt * 8 + cpair) * 4);
            const int keyc = key_base + nt * 8 + cpair;

            float p0 = score_p(sacc[nt][0], q00, k0p.x, invk, c1);
            float p1 = score_p(sacc[nt][1], q00, k0p.y, invk, c1);
            float p2 = score_p(sacc[nt][2], q01, k0p.x, invk, c1);
            float p3 = score_p(sacc[nt][3], q01, k0p.y, invk, c1);
            if (maskT) {
                if (keyc     > qr0) p0 = 0.0f;
                if (keyc + 1 > qr0) p1 = 0.0f;
                if (keyc     > qr1) p2 = 0.0f;
                if (keyc + 1 > qr1) p3 = 0.0f;
            }
            ls0 += p0 + p1;
            ls1 += p2 + p3;

            const int g = nt >> 1;
            const int rb = (nt & 1) * 2;
            pa[g][rb + 0] = pack_h2(p0, p1);
            pa[g][rb + 1] = pack_h2(p2, p3);
        }

#pragma unroll
        for (int g = 0; g < 4; g++) {
            uint32_t vf[8][2];
#pragma unroll
            for (int dt = 0; dt < 8; dt++)
                ldm_x2t(vf[dt][0], vf[dt][1], sVh + vfb + g * 16 * AROWB + dt * 16);
#pragma unroll
            for (int dt = 0; dt < 8; dt++) mma16816h(O[dt], pa[g], vf[dt]);
        }
    }

    ls0 += __shfl_xor_sync(0xffffffffu, ls0, 1);
    ls0 += __shfl_xor_sync(0xffffffffu, ls0, 2);
    ls1 += __shfl_xor_sync(0xffffffffu, ls1, 1);
    ls1 += __shfl_xor_sync(0xffffffffu, ls1, 2);
    const float n0 = 1.0f / ls0;
    const float n1 = 1.0f / ls1;

    const size_t o0 = ((size_t)b * T_ + qr0) * C_ + h * 64;
    const size_t o1 = ((size_t)b * T_ + qr1) * C_ + h * 64;
#pragma unroll
    for (int dt = 0; dt < 8; dt++) {
        const int c = dt * 8 + cpair;
        *(uint32_t*)(g_oh + o0 + c) = pack_h2(O[dt][0] * n0, O[dt][1] * n0);
        *(uint32_t*)(g_oh + o1 + c) = pack_h2(O[dt][2] * n1, O[dt][3] * n1);
    }
}

// ---------------- launch ------------------------------------------------------
extern "C" void kernel_launch(void* const* d_in, const int* in_sizes, int n_in,
                              void* d_out, int out_size)
{
    const float* x    = (const float*)d_in[0];
    const float* Wqkv = (const float*)d_in[1];
    const float* Wout = (const float*)d_in[2];
    const float* hyp  = (const float*)d_in[3];
    float* out = (float*)d_out;

    static __half *p_xh = nullptr, *p_w1h, *p_w2h, *p_oh;
    if (!p_xh) {
        cudaGetSymbolAddress((void**)&p_xh, g_xh);
        cudaGetSymbolAddress((void**)&p_w1h, g_w1h);
        cudaGetSymbolAddress((void**)&p_w2h, g_w2h);
        cudaGetSymbolAddress((void**)&p_oh, g_oh);
        cudaFuncSetAttribute(gemm_qkv,
                             cudaFuncAttributeMaxDynamicSharedMemorySize, GSM);
        cudaFuncSetAttribute(gemm_hf,
                             cudaFuncAttributeMaxDynamicSharedMemorySize, GSM);
        cudaFuncSetAttribute(attn_mma,
                             cudaFuncAttributeMaxDynamicSharedMemorySize, ATT_SMEM);
    }

    // 0) conversions + cos/sin table
    build_cs<<<128, 256>>>();
    cvt_h<<<(4096 * 1024 / 4 + 255) / 256, 256>>>(x, p_xh, 4096 * 1024 / 4);
    cvt_h<<<(3072 * 1024 / 4 + 255) / 256, 256>>>(Wqkv, p_w1h, 3072 * 1024 / 4);
    cvt_h<<<(1024 * 1024 / 4 + 255) / 256, 256>>>(Wout, p_w2h, 1024 * 1024 / 4);

    // 1) qkv = x @ W_qkv^T with fused RoPE/split/norm epilogue (K-chunk 64)
    gemm_qkv<<<dim3(3072 / 256, 4096 / 128), 256, GSM>>>(p_xh, p_w1h, hyp);

    // 2) tensorized attention
    attn_mma<<<dim3(T_ / 128, H_, B_), 256, ATT_SMEM>>>(hyp);

    // 3) out = o @ W_out^T (K-chunk 64)
    gemm_hf<<<dim3(1024 / 256, 4096 / 128), 256, GSM>>>(
        p_oh, p_w2h, out, 4096, 1024, 1024);
}